// round 9
// baseline (speedup 1.0000x reference)
#include <cuda_runtime.h>
#include <cuda_fp16.h>
#include <cstdint>
#include <cstddef>

#define D 128
#define HID 384
#define MAXN 100000
#define MAXE 500000
#define MAXG 5000

// ---------------------------------------------------------------------------
// Scratch layout (floats)
// ---------------------------------------------------------------------------
static const size_t OFF_ZB = 0;
static const size_t OFF_PH = OFF_ZB + (size_t)MAXE * HID;
static const size_t OFF_U1 = OFF_PH + (size_t)MAXN * HID;
static const size_t OFF_XA = OFF_U1 + (size_t)MAXG * HID;
static const size_t OFF_ZA = OFF_XA + (size_t)MAXN * HID;
static const size_t OFF_XG = OFF_ZA + (size_t)MAXN * HID;
static const size_t OFF_ZG = OFF_XG + (size_t)MAXG * HID;
static const size_t OFF_SH = OFF_ZG + (size_t)MAXG * HID;
static const size_t OFF_SE = OFF_SH + (size_t)MAXN * D;
static const size_t OFF_UH = OFF_SE + (size_t)MAXN * D;
static const size_t OFF_UE = OFF_UH + (size_t)MAXG * D;
static const size_t OFF_ST = OFF_UE + (size_t)MAXG * D;
static const size_t OFF_WP = OFF_ST + 4 * HID;   // prepped weights (fp16)
static const size_t WP_FLOATS = 294912;          // 589,824 halves
static const size_t TOTAL_SCRATCH = OFF_WP + WP_FLOATS;

__device__ float g_scratch[TOTAL_SCRATCH];

// Prepped-weight offsets in half elements (dense fp16).
#define WPO_BW1A 0
#define WPO_BW1B 49152
#define WPO_BW1C 98304
#define WPO_BW2  147456
#define WPO_AW1  196608
#define WPO_AW2  344064
#define WPO_GW1  393216
#define WPO_GW2  540672

// ---------------------------------------------------------------------------
// PTX helpers (arch-agnostic: ldmatrix sm_75+, fp16 mma sm_80+, cp.async sm_80+)
// ---------------------------------------------------------------------------
__device__ __forceinline__ uint32_t smem_u32(const void* p) {
    uint32_t a;
    asm("{ .reg .u64 t; cvta.to.shared.u64 t, %1; cvt.u32.u64 %0, t; }" : "=r"(a) : "l"(p));
    return a;
}
__device__ __forceinline__ void ldsm4(uint32_t (&r)[4], uint32_t addr) {
    asm volatile("ldmatrix.sync.aligned.m8n8.x4.shared.b16 {%0,%1,%2,%3}, [%4];"
                 : "=r"(r[0]), "=r"(r[1]), "=r"(r[2]), "=r"(r[3]) : "r"(addr));
}
__device__ __forceinline__ void ldsm4t(uint32_t (&r)[4], uint32_t addr) {
    asm volatile("ldmatrix.sync.aligned.m8n8.x4.trans.shared.b16 {%0,%1,%2,%3}, [%4];"
                 : "=r"(r[0]), "=r"(r[1]), "=r"(r[2]), "=r"(r[3]) : "r"(addr));
}
__device__ __forceinline__ void mma16816(float (&c)[4], const uint32_t (&a)[4],
                                         uint32_t b0, uint32_t b1) {
    asm volatile(
        "mma.sync.aligned.m16n8k16.row.col.f32.f16.f16.f32 "
        "{%0,%1,%2,%3}, {%4,%5,%6,%7}, {%8,%9}, {%0,%1,%2,%3};"
        : "+f"(c[0]), "+f"(c[1]), "+f"(c[2]), "+f"(c[3])
        : "r"(a[0]), "r"(a[1]), "r"(a[2]), "r"(a[3]), "r"(b0), "r"(b1));
}
__device__ __forceinline__ uint32_t packh2(float x, float y) {
    __half2 p = __halves2half2(__float2half_rn(x), __float2half_rn(y));
    return *(uint32_t*)&p;
}
__device__ __forceinline__ void cp_async16(uint32_t saddr, const void* gaddr) {
    asm volatile("cp.async.cg.shared.global [%0], [%1], 16;" :: "r"(saddr), "l"(gaddr));
}
__device__ __forceinline__ void cp_commit() {
    asm volatile("cp.async.commit_group;" ::: "memory");
}
__device__ __forceinline__ void cp_wait0() {
    asm volatile("cp.async.wait_group 0;" ::: "memory");
}

// ---------------------------------------------------------------------------
// Weight prep: fp32 W -> dense fp16
// ---------------------------------------------------------------------------
__global__ void prep_weight(const float* __restrict__ W, __half* __restrict__ out,
                            int total)
{
    int i = blockIdx.x * blockDim.x + threadIdx.x;
    if (i >= total) return;
    out[i] = __float2half_rn(W[i]);
}

// ---------------------------------------------------------------------------
// Dynamic SMEM layout (bytes). APAD/BPAD give conflict-free ldmatrix phases.
// ---------------------------------------------------------------------------
#define APAD 80     // bytes per A smem row (32 fp16 = 64B + 16B pad)
#define BPAD 272    // bytes per B smem row (128 fp16 = 256B + 16B pad)
#define SM_AHI  0               // 2 x 128*80 = 20480
#define SM_ALO  20480           // 2 x 128*80 = 20480
#define SM_B    40960           // 2 x 32*272 = 17408
#define SM_SSC  58368           // 384 floats
#define SM_SSH  59904           // 384 floats
#define SM_SSUM 61440           // 128 floats
#define SM_SSQ  61952           // 128 floats
#define SM_TOTAL 62464

// ---------------------------------------------------------------------------
// mma.sync GEMM: C[M,Nd] = op(A)[M,K] @ W[K,Nd] (+bias)
// fp16 2-pass split: A = Ahi + Alo (exact), B = fp16(W). fp32 accumulate.
// 128x128 tile, 256 threads (8 warps as 4x2; warp tile 32x64), KC=32.
// 2 CTAs/SM; A and B double-buffered; ONE __syncthreads per chunk.
// RACE-FIX vs R8: the B cp.async for chunk c+1 is issued AFTER the per-chunk
// __syncthreads, so every thread's chunk c-1 reads of that buffer are
// barrier-ordered before the overwrite. cp_wait0 runs BEFORE the sync so the
// landed B chunk is published to all threads by the same barrier.
// ---------------------------------------------------------------------------
template<bool BNA, bool SCAT, bool GATH, bool STATS>
__global__ void __launch_bounds__(256, 2)
gemm_mma(const float* __restrict__ A, const __half* __restrict__ Bp,
         const float* __restrict__ bias, float* __restrict__ C,
         int M, int K, int Nd,
         const float* __restrict__ bnscale, const float* __restrict__ bnshift,
         const int* __restrict__ seg, float* __restrict__ segout,
         const float* __restrict__ Ph, const float* __restrict__ U1,
         const int* __restrict__ src, const int* __restrict__ dst,
         const int* __restrict__ gid,
         float* __restrict__ st_sum, float* __restrict__ st_sq)
{
    extern __shared__ __align__(16) char smem[];
    float* ssc  = (float*)(smem + SM_SSC);
    float* ssh  = (float*)(smem + SM_SSH);
    float* ssum = (float*)(smem + SM_SSUM);
    float* ssq  = (float*)(smem + SM_SSQ);

    const int tid  = threadIdx.x;
    const int wid  = tid >> 5;
    const int lane = tid & 31;
    const int wm   = wid & 3;     // warp row (32 rows)
    const int wn   = wid >> 2;    // warp col (64 cols)
    const int row0 = blockIdx.y * 128;
    const int col0 = blockIdx.x * 128;

    if (BNA) {
        for (int i = tid; i < K; i += 256) { ssc[i] = bnscale[i]; ssh[i] = bnshift[i]; }
    }
    if (STATS && tid < 128) { ssum[tid] = 0.f; ssq[tid] = 0.f; }

    // ---- staging thread mapping ----
    const int arow = tid >> 1;            // 0..127
    const int acol = (tid & 1) * 16;      // 0 or 16
    const bool avalid = (row0 + arow) < M;
    const float* Ap = A + (size_t)(row0 + arow) * K + acol;

    const int brow = tid >> 3;            // 0..31
    const int bcol = (tid & 7) * 16;      // 0..112

    float acc[2][8][4];
    #pragma unroll
    for (int i = 0; i < 2; i++)
        #pragma unroll
        for (int j = 0; j < 8; j++)
            #pragma unroll
            for (int q = 0; q < 4; q++) acc[i][j][q] = 0.f;

    const uint32_t sbase = smem_u32(smem);
    const uint32_t aoff = (uint32_t)((lane & 15) * APAD + (lane >> 4) * 16);
    const uint32_t boff = (uint32_t)((((lane >> 3) & 1) * 8 + (lane & 7)) * BPAD + (lane >> 4) * 16);

    const int nchunk = K >> 5;
    const uint32_t bdst = (uint32_t)(brow * BPAD + bcol * 2);

    // issue B chunk 0 into buffer 0 (buffer untouched so far; no race)
    cp_async16(sbase + SM_B + bdst,      Bp + (size_t)brow * Nd + col0 + bcol);
    cp_async16(sbase + SM_B + bdst + 16, Bp + (size_t)brow * Nd + col0 + bcol + 8);
    cp_commit();

    __syncthreads();   // publishes ssc/ssh/ssum

    // prefetch + convert A chunk 0 into registers
    uint2 ch[4], cl[4];
    #pragma unroll
    for (int q = 0; q < 4; q++) { ch[q] = make_uint2(0u, 0u); cl[q] = make_uint2(0u, 0u); }
    if (avalid) {
        #pragma unroll
        for (int q = 0; q < 4; q++) {
            float4 v = *(const float4*)(Ap + q * 4);
            if (BNA) {
                const int k = acol + q * 4;
                v.x = fmaxf(fmaf(v.x, ssc[k + 0], ssh[k + 0]), 0.f);
                v.y = fmaxf(fmaf(v.y, ssc[k + 1], ssh[k + 1]), 0.f);
                v.z = fmaxf(fmaf(v.z, ssc[k + 2], ssh[k + 2]), 0.f);
                v.w = fmaxf(fmaf(v.w, ssc[k + 3], ssh[k + 3]), 0.f);
            }
            float hx = __half2float(__float2half_rn(v.x));
            float hy = __half2float(__float2half_rn(v.y));
            float hz = __half2float(__float2half_rn(v.z));
            float hw = __half2float(__float2half_rn(v.w));
            ch[q].x = packh2(v.x, v.y);
            ch[q].y = packh2(v.z, v.w);
            cl[q].x = packh2(v.x - hx, v.y - hy);
            cl[q].y = packh2(v.z - hz, v.w - hw);
        }
    }

    for (int c = 0; c < nchunk; c++) {
        const int buf = c & 1;
        // ---- store converted A regs into buffer buf ----
        {
            char* ah = smem + SM_AHI + buf * 10240 + arow * APAD + acol * 2;
            char* al = smem + SM_ALO + buf * 10240 + arow * APAD + acol * 2;
            #pragma unroll
            for (int q = 0; q < 4; q++) {
                *(uint2*)(ah + q * 8) = ch[q];
                *(uint2*)(al + q * 8) = cl[q];
            }
        }
        // ---- B chunk c has landed (single group in flight) ----
        cp_wait0();
        __syncthreads();    // publishes A buf stores + B chunk c to all threads
        // ---- issue B chunk c+1 (safe: all chunk c-1 reads ordered before) ----
        if (c + 1 < nchunk) {
            const uint32_t nb = sbase + SM_B + (uint32_t)(((c + 1) & 1) * 8704);
            const __half* bp = Bp + (size_t)((c + 1) * 32 + brow) * Nd + col0 + bcol;
            cp_async16(nb + bdst, bp);
            cp_async16(nb + bdst + 16, bp + 8);
            cp_commit();
        }
        // ---- prefetch + convert A chunk c+1 (overlaps following MMAs) ----
        if (c + 1 < nchunk && avalid) {
            const float* ap = Ap + (c + 1) * 32;
            #pragma unroll
            for (int q = 0; q < 4; q++) {
                float4 v = *(const float4*)(ap + q * 4);
                if (BNA) {
                    const int k = (c + 1) * 32 + acol + q * 4;
                    v.x = fmaxf(fmaf(v.x, ssc[k + 0], ssh[k + 0]), 0.f);
                    v.y = fmaxf(fmaf(v.y, ssc[k + 1], ssh[k + 1]), 0.f);
                    v.z = fmaxf(fmaf(v.z, ssc[k + 2], ssh[k + 2]), 0.f);
                    v.w = fmaxf(fmaf(v.w, ssc[k + 3], ssh[k + 3]), 0.f);
                }
                float hx = __half2float(__float2half_rn(v.x));
                float hy = __half2float(__float2half_rn(v.y));
                float hz = __half2float(__float2half_rn(v.z));
                float hw = __half2float(__float2half_rn(v.w));
                ch[q].x = packh2(v.x, v.y);
                ch[q].y = packh2(v.z, v.w);
                cl[q].x = packh2(v.x - hx, v.y - hy);
                cl[q].y = packh2(v.z - hz, v.w - hw);
            }
        }
        // ---- compute chunk c ----
        const uint32_t aHiC = sbase + SM_AHI + (uint32_t)(buf * 10240);
        const uint32_t aLoC = sbase + SM_ALO + (uint32_t)(buf * 10240);
        const uint32_t bC   = sbase + SM_B   + (uint32_t)(buf * 8704);
        #pragma unroll
        for (int kk = 0; kk < 2; kk++) {
            uint32_t af[2][4], bx[8][2];
            #pragma unroll
            for (int p = 0; p < 4; p++) {
                uint32_t r[4];
                ldsm4t(r, bC + boff + (uint32_t)(kk * 16 * BPAD + (64 * wn + p * 16) * 2));
                bx[2 * p][0] = r[0]; bx[2 * p][1] = r[1];
                bx[2 * p + 1][0] = r[2]; bx[2 * p + 1][1] = r[3];
            }
            #pragma unroll
            for (int i = 0; i < 2; i++)
                ldsm4(af[i], aHiC + aoff + (uint32_t)((32 * wm + 16 * i) * APAD + kk * 32));
            #pragma unroll
            for (int i = 0; i < 2; i++)
                #pragma unroll
                for (int j = 0; j < 8; j++)
                    mma16816(acc[i][j], af[i], bx[j][0], bx[j][1]);
            #pragma unroll
            for (int i = 0; i < 2; i++)
                ldsm4(af[i], aLoC + aoff + (uint32_t)((32 * wm + 16 * i) * APAD + kk * 32));
            #pragma unroll
            for (int i = 0; i < 2; i++)
                #pragma unroll
                for (int j = 0; j < 8; j++)
                    mma16816(acc[i][j], af[i], bx[j][0], bx[j][1]);
        }
        // no trailing sync: next iter writes the OTHER A buffer (ordered by
        // sync c+1 against this iter's reads) and B writes are post-sync.
    }

    // ---- epilogue ----
    const int m4 = lane >> 2;
    const int n2 = (lane & 3) * 2;

    float bcolv[16];
    #pragma unroll
    for (int j = 0; j < 8; j++) {
        if (bias) {
            float2 b2 = *(const float2*)(bias + col0 + 64 * wn + 8 * j + n2);
            bcolv[2 * j] = b2.x; bcolv[2 * j + 1] = b2.y;
        } else {
            bcolv[2 * j] = 0.f; bcolv[2 * j + 1] = 0.f;
        }
    }
    float csum[16], csq[16];
    if (STATS) {
        #pragma unroll
        for (int q = 0; q < 16; q++) { csum[q] = 0.f; csq[q] = 0.f; }
    }

    #pragma unroll
    for (int i = 0; i < 2; i++) {
        const int rb = row0 + 32 * wm + 16 * i + m4;
        #pragma unroll
        for (int hf = 0; hf < 2; hf++) {
            const int r = rb + 8 * hf;
            if (r >= M) continue;
            int si = 0, di = 0, gi2 = 0, sg = 0;
            if (GATH) { si = src[r]; di = dst[r]; gi2 = gid[si]; }
            if (SCAT) sg = seg[r];
            #pragma unroll
            for (int j = 0; j < 8; j++) {
                const int gc = col0 + 64 * wn + 8 * j + n2;
                float v0 = acc[i][j][2 * hf]     + bcolv[2 * j];
                float v1 = acc[i][j][2 * hf + 1] + bcolv[2 * j + 1];
                if (GATH) {
                    float2 g1 = *(const float2*)(Ph + (size_t)si * HID + gc);
                    float2 g2 = *(const float2*)(Ph + (size_t)di * HID + gc);
                    float2 g3 = *(const float2*)(U1 + (size_t)gi2 * HID + gc);
                    v0 += g1.x + g2.x + g3.x;
                    v1 += g1.y + g2.y + g3.y;
                }
                *(float2*)(C + (size_t)r * Nd + gc) = make_float2(v0, v1);
                if (SCAT) {
                    float* so = segout + (size_t)sg * Nd + gc;
                    atomicAdd(so, v0); atomicAdd(so + 1, v1);
                }
                if (STATS) {
                    csum[2 * j] += v0;     csq[2 * j] += v0 * v0;
                    csum[2 * j + 1] += v1; csq[2 * j + 1] += v1 * v1;
                }
            }
        }
    }
    if (STATS) {
        #pragma unroll
        for (int j = 0; j < 8; j++) {
            const int cl0 = 64 * wn + 8 * j + n2;
            atomicAdd(&ssum[cl0], csum[2 * j]);
            atomicAdd(&ssum[cl0 + 1], csum[2 * j + 1]);
            atomicAdd(&ssq[cl0], csq[2 * j]);
            atomicAdd(&ssq[cl0 + 1], csq[2 * j + 1]);
        }
        __syncthreads();
        if (tid < 128) {
            atomicAdd(&st_sum[col0 + tid], ssum[tid]);
            atomicAdd(&st_sq[col0 + tid], ssq[tid]);
        }
    }
}

// ---------------------------------------------------------------------------
// Elementwise / scatter kernels
// ---------------------------------------------------------------------------
__global__ void zerok(float* __restrict__ p, size_t n) {
    size_t i = (size_t)blockIdx.x * blockDim.x + threadIdx.x;
    size_t st = (size_t)gridDim.x * blockDim.x;
    for (; i < n; i += st) p[i] = 0.f;
}

__global__ void edge_scatter_h(const float* __restrict__ h, const int* __restrict__ src,
                               const int* __restrict__ dst, float* __restrict__ SH, int E)
{
    int idx = blockIdx.x * blockDim.x + threadIdx.x;
    int tot = E * 32;
    if (idx >= tot) return;
    int ei = idx >> 5;
    int c  = (idx & 31) << 2;
    int s = src[ei], d = dst[ei];
    float4 v = *(const float4*)&h[(size_t)s * D + c];
    float* o = SH + (size_t)d * D + c;
    atomicAdd(o + 0, v.x); atomicAdd(o + 1, v.y);
    atomicAdd(o + 2, v.z); atomicAdd(o + 3, v.w);
}

__global__ void bn_prep(float* __restrict__ sum, float* __restrict__ sq,
                        const float* __restrict__ g1, const float* __restrict__ beta1,
                        float* __restrict__ scale, float* __restrict__ shift, float invM)
{
    const int c = threadIdx.x;
    float mean = sum[c] * invM;
    float var  = sq[c] * invM - mean * mean;
    float rstd = rsqrtf(var + 1e-5f);
    float sc = rstd * g1[c];
    scale[c] = sc;
    shift[c] = beta1[c] - mean * sc;
    sum[c] = 0.f;
    sq[c] = 0.f;
}

__global__ void node_build(const float* __restrict__ h, const float* __restrict__ u,
                           const int* __restrict__ gid,
                           const float* __restrict__ SH, const float* __restrict__ SE,
                           float* __restrict__ Xa, float* __restrict__ UE, int N)
{
    int idx = blockIdx.x * blockDim.x + threadIdx.x;
    int tot = N * 32;
    if (idx >= tot) return;
    int n = idx >> 5;
    int c = (idx & 31) << 2;
    int g = gid[n];
    float4 sh = *(const float4*)&SH[(size_t)n * D + c];
    float4 hv = *(const float4*)&h[(size_t)n * D + c];
    float4 se = *(const float4*)&SE[(size_t)n * D + c];
    float4 uv = *(const float4*)&u[(size_t)g * D + c];
    size_t base = (size_t)n * HID;
    *(float4*)&Xa[base + c]         = make_float4(sh.x + hv.x, sh.y + hv.y, sh.z + hv.z, sh.w + hv.w);
    *(float4*)&Xa[base + D + c]     = se;
    *(float4*)&Xa[base + 2 * D + c] = uv;
    float* o = UE + (size_t)g * D + c;
    atomicAdd(o + 0, 0.5f * se.x); atomicAdd(o + 1, 0.5f * se.y);
    atomicAdd(o + 2, 0.5f * se.z); atomicAdd(o + 3, 0.5f * se.w);
}

__global__ void graph_build(const float* __restrict__ u, const float* __restrict__ UH,
                            const float* __restrict__ UE, float* __restrict__ Xg, int G)
{
    int idx = blockIdx.x * blockDim.x + threadIdx.x;
    int tot = G * 32;
    if (idx >= tot) return;
    int g = idx >> 5;
    int c = (idx & 31) << 2;
    size_t base = (size_t)g * HID;
    *(float4*)&Xg[base + c]         = *(const float4*)&UH[(size_t)g * D + c];
    *(float4*)&Xg[base + D + c]     = *(const float4*)&UE[(size_t)g * D + c];
    *(float4*)&Xg[base + 2 * D + c] = *(const float4*)&u[(size_t)g * D + c];
}

// ---------------------------------------------------------------------------
// Dispatch. mode: 0 plain, 1 GATH+STATS, 2 BNA+SCAT, 3 STATS, 4 BNA
// ---------------------------------------------------------------------------
static void run_gemm_mma(int mode,
                         const float* A, const __half* Bp, const float* bias, float* C,
                         int M, int K, int Nd,
                         const float* sc, const float* sh,
                         const int* seg, float* segout,
                         const float* Ph, const float* U1,
                         const int* src, const int* dst, const int* gid,
                         float* st_sum, float* st_sq)
{
    dim3 grid(Nd / 128, (M + 127) / 128);
    switch (mode) {
    case 0:
        cudaFuncSetAttribute(gemm_mma<false,false,false,false>, cudaFuncAttributeMaxDynamicSharedMemorySize, SM_TOTAL);
        gemm_mma<false,false,false,false><<<grid,256,SM_TOTAL>>>(A,Bp,bias,C,M,K,Nd,sc,sh,seg,segout,Ph,U1,src,dst,gid,st_sum,st_sq);
        break;
    case 1:
        cudaFuncSetAttribute(gemm_mma<false,false,true,true>, cudaFuncAttributeMaxDynamicSharedMemorySize, SM_TOTAL);
        gemm_mma<false,false,true, true ><<<grid,256,SM_TOTAL>>>(A,Bp,bias,C,M,K,Nd,sc,sh,seg,segout,Ph,U1,src,dst,gid,st_sum,st_sq);
        break;
    case 2:
        cudaFuncSetAttribute(gemm_mma<true,true,false,false>, cudaFuncAttributeMaxDynamicSharedMemorySize, SM_TOTAL);
        gemm_mma<true, true, false,false><<<grid,256,SM_TOTAL>>>(A,Bp,bias,C,M,K,Nd,sc,sh,seg,segout,Ph,U1,src,dst,gid,st_sum,st_sq);
        break;
    case 3:
        cudaFuncSetAttribute(gemm_mma<false,false,false,true>, cudaFuncAttributeMaxDynamicSharedMemorySize, SM_TOTAL);
        gemm_mma<false,false,false,true ><<<grid,256,SM_TOTAL>>>(A,Bp,bias,C,M,K,Nd,sc,sh,seg,segout,Ph,U1,src,dst,gid,st_sum,st_sq);
        break;
    case 4:
        cudaFuncSetAttribute(gemm_mma<true,false,false,false>, cudaFuncAttributeMaxDynamicSharedMemorySize, SM_TOTAL);
        gemm_mma<true, false,false,false><<<grid,256,SM_TOTAL>>>(A,Bp,bias,C,M,K,Nd,sc,sh,seg,segout,Ph,U1,src,dst,gid,st_sum,st_sq);
        break;
    }
}

extern "C" void kernel_launch(void* const* d_in, const int* in_sizes, int n_in,
                              void* d_out, int out_size)
{
    const float* h   = (const float*)d_in[0];
    const float* e   = (const float*)d_in[1];
    const float* u   = (const float*)d_in[2];
    const int*   src = (const int*)d_in[3];
    const int*   dst = (const int*)d_in[4];
    const int*   gid = (const int*)d_in[5];

    const float* bW1 = (const float*)d_in[6];
    const float* bb1 = (const float*)d_in[7];
    const float* bg1 = (const float*)d_in[8];
    const float* bbt = (const float*)d_in[9];
    const float* bW2 = (const float*)d_in[10];
    const float* bb2 = (const float*)d_in[11];

    const float* aW1 = (const float*)d_in[12];
    const float* ab1 = (const float*)d_in[13];
    const float* ag1 = (const float*)d_in[14];
    const float* abt = (const float*)d_in[15];
    const float* aW2 = (const float*)d_in[16];
    const float* ab2 = (const float*)d_in[17];

    const float* gW1 = (const float*)d_in[18];
    const float* gb1 = (const float*)d_in[19];
    const float* gg1 = (const float*)d_in[20];
    const float* gbt = (const float*)d_in[21];
    const float* gW2 = (const float*)d_in[22];
    const float* gb2 = (const float*)d_in[23];

    const int N = in_sizes[5];
    const int E = in_sizes[3];
    const int G = in_sizes[2] / D;

    float* scratch = nullptr;
    cudaGetSymbolAddress((void**)&scratch, g_scratch);

    float* Zb = scratch + OFF_ZB;
    float* Ph = scratch + OFF_PH;
    float* U1 = scratch + OFF_U1;
    float* Xa = scratch + OFF_XA;
    float* Za = scratch + OFF_ZA;
    float* Xg = scratch + OFF_XG;
    float* Zg = scratch + OFF_ZG;
    float* SH = scratch + OFF_SH;
    float* SE = scratch + OFF_SE;
    float* UH = scratch + OFF_UH;
    float* UE = scratch + OFF_UE;
    float* st_sum   = scratch + OFF_ST;
    float* st_sq    = st_sum + HID;
    float* bn_scale = st_sq + HID;
    float* bn_shift = bn_scale + HID;
    __half* WP = (__half*)(scratch + OFF_WP);

    float* out_h = (float*)d_out;
    float* out_e = out_h + (size_t)N * D;
    float* out_u = out_e + (size_t)E * D;

    // Zero accumulators (SH, SE, UH, UE, stats) — contiguous region.
    {
        size_t nz = (size_t)MAXN * D * 2 + (size_t)MAXG * D * 2 + 2 * HID;
        zerok<<<2048, 256>>>(SH, nz);
    }

    // Pre-convert all weights to dense fp16.
    {
        const int T1 = 128 * HID, T2 = HID * HID, T3 = HID * D;
        prep_weight<<<(T1 + 255) / 256, 256>>>(bW1,                       WP + WPO_BW1A, T1);
        prep_weight<<<(T1 + 255) / 256, 256>>>(bW1 + (size_t)D * HID,     WP + WPO_BW1B, T1);
        prep_weight<<<(T1 + 255) / 256, 256>>>(bW1 + (size_t)2 * D * HID, WP + WPO_BW1C, T1);
        prep_weight<<<(T3 + 255) / 256, 256>>>(bW2, WP + WPO_BW2, T3);
        prep_weight<<<(T2 + 255) / 256, 256>>>(aW1, WP + WPO_AW1, T2);
        prep_weight<<<(T3 + 255) / 256, 256>>>(aW2, WP + WPO_AW2, T3);
        prep_weight<<<(T2 + 255) / 256, 256>>>(gW1, WP + WPO_GW1, T2);
        prep_weight<<<(T3 + 255) / 256, 256>>>(gW2, WP + WPO_GW2, T3);
    }

    // ---- Bond path ----
    run_gemm_mma(0, h, WP + WPO_BW1A, nullptr, Ph, N, 128, HID,
                 nullptr, nullptr, nullptr, nullptr, nullptr, nullptr, nullptr, nullptr, nullptr, nullptr, nullptr);
    run_gemm_mma(0, u, WP + WPO_BW1C, bb1, U1, G, 128, HID,
                 nullptr, nullptr, nullptr, nullptr, nullptr, nullptr, nullptr, nullptr, nullptr, nullptr, nullptr);
    edge_scatter_h<<<(E * 32 + 255) / 256, 256>>>(h, src, dst, SH, E);
    // Zb = e@bW1b + Ph[src] + Ph[dst] + U1[gid[src]]; fused stats
    run_gemm_mma(1, e, WP + WPO_BW1B, nullptr, Zb, E, 128, HID,
                 nullptr, nullptr, nullptr, nullptr, Ph, U1, src, dst, gid, st_sum, st_sq);
    bn_prep<<<1, HID>>>(st_sum, st_sq, bg1, bbt, bn_scale, bn_shift, 1.f / (float)E);
    // e_new = relu(BN(Zb)) @ bW2 + bb2 ; SE[dst] += e_new
    run_gemm_mma(2, Zb, WP + WPO_BW2, bb2, out_e, E, HID, D,
                 bn_scale, bn_shift, dst, SE, nullptr, nullptr, nullptr, nullptr, nullptr, nullptr, nullptr);

    // ---- Atom path ----
    node_build<<<(N * 32 + 255) / 256, 256>>>(h, u, gid, SH, SE, Xa, UE, N);
    run_gemm_mma(3, Xa, WP + WPO_AW1, ab1, Za, N, HID, HID,
                 nullptr, nullptr, nullptr, nullptr, nullptr, nullptr, nullptr, nullptr, nullptr, st_sum, st_sq);
    bn_prep<<<1, HID>>>(st_sum, st_sq, ag1, abt, bn_scale, bn_shift, 1.f / (float)N);
    run_gemm_mma(2, Za, WP + WPO_AW2, ab2, out_h, N, HID, D,
                 bn_scale, bn_shift, gid, UH, nullptr, nullptr, nullptr, nullptr, nullptr, nullptr, nullptr);

    // ---- Global path ----
    graph_build<<<(G * 32 + 255) / 256, 256>>>(u, UH, UE, Xg, G);
    run_gemm_mma(3, Xg, WP + WPO_GW1, gb1, Zg, G, HID, HID,
                 nullptr, nullptr, nullptr, nullptr, nullptr, nullptr, nullptr, nullptr, nullptr, st_sum, st_sq);
    bn_prep<<<1, HID>>>(st_sum, st_sq, gg1, gbt, bn_scale, bn_shift, 1.f / (float)G);
    run_gemm_mma(4, Zg, WP + WPO_GW2, gb2, out_u, G, HID, D,
                 bn_scale, bn_shift, nullptr, nullptr, nullptr, nullptr, nullptr, nullptr, nullptr, nullptr, nullptr);
}

// round 10
// speedup vs baseline: 1.1272x; 1.1272x over previous
#include <cuda_runtime.h>
#include <cuda_fp16.h>
#include <cstdint>
#include <cstddef>

#define D 128
#define HID 384
#define MAXN 100000
#define MAXE 500000
#define MAXG 5000

// ---------------------------------------------------------------------------
// Scratch layout (floats)
// ---------------------------------------------------------------------------
static const size_t OFF_ZB = 0;
static const size_t OFF_PH = OFF_ZB + (size_t)MAXE * HID;
static const size_t OFF_U1 = OFF_PH + (size_t)MAXN * HID;
static const size_t OFF_XA = OFF_U1 + (size_t)MAXG * HID;
static const size_t OFF_ZA = OFF_XA + (size_t)MAXN * HID;
static const size_t OFF_XG = OFF_ZA + (size_t)MAXN * HID;
static const size_t OFF_ZG = OFF_XG + (size_t)MAXG * HID;
static const size_t OFF_SH = OFF_ZG + (size_t)MAXG * HID;
static const size_t OFF_SE = OFF_SH + (size_t)MAXN * D;
static const size_t OFF_UH = OFF_SE + (size_t)MAXN * D;
static const size_t OFF_UE = OFF_UH + (size_t)MAXG * D;
static const size_t OFF_ST = OFF_UE + (size_t)MAXG * D;
static const size_t OFF_WP = OFF_ST + 4 * HID;   // prepped weights (fp16)
static const size_t WP_FLOATS = 294912;          // 589,824 halves
static const size_t TOTAL_SCRATCH = OFF_WP + WP_FLOATS;

__device__ float g_scratch[TOTAL_SCRATCH];

// Prepped-weight offsets in half elements (dense fp16).
#define WPO_BW1A 0
#define WPO_BW1B 49152
#define WPO_BW1C 98304
#define WPO_BW2  147456
#define WPO_AW1  196608
#define WPO_AW2  344064
#define WPO_GW1  393216
#define WPO_GW2  540672

// ---------------------------------------------------------------------------
// PTX helpers (arch-agnostic: ldmatrix sm_75+, fp16 mma sm_80+, cp.async sm_80+)
// ---------------------------------------------------------------------------
__device__ __forceinline__ uint32_t smem_u32(const void* p) {
    uint32_t a;
    asm("{ .reg .u64 t; cvta.to.shared.u64 t, %1; cvt.u32.u64 %0, t; }" : "=r"(a) : "l"(p));
    return a;
}
__device__ __forceinline__ void ldsm4(uint32_t (&r)[4], uint32_t addr) {
    asm volatile("ldmatrix.sync.aligned.m8n8.x4.shared.b16 {%0,%1,%2,%3}, [%4];"
                 : "=r"(r[0]), "=r"(r[1]), "=r"(r[2]), "=r"(r[3]) : "r"(addr));
}
__device__ __forceinline__ void ldsm4t(uint32_t (&r)[4], uint32_t addr) {
    asm volatile("ldmatrix.sync.aligned.m8n8.x4.trans.shared.b16 {%0,%1,%2,%3}, [%4];"
                 : "=r"(r[0]), "=r"(r[1]), "=r"(r[2]), "=r"(r[3]) : "r"(addr));
}
__device__ __forceinline__ void mma16816(float (&c)[4], const uint32_t (&a)[4],
                                         uint32_t b0, uint32_t b1) {
    asm volatile(
        "mma.sync.aligned.m16n8k16.row.col.f32.f16.f16.f32 "
        "{%0,%1,%2,%3}, {%4,%5,%6,%7}, {%8,%9}, {%0,%1,%2,%3};"
        : "+f"(c[0]), "+f"(c[1]), "+f"(c[2]), "+f"(c[3])
        : "r"(a[0]), "r"(a[1]), "r"(a[2]), "r"(a[3]), "r"(b0), "r"(b1));
}
__device__ __forceinline__ uint32_t packh2(float x, float y) {
    __half2 p = __halves2half2(__float2half_rn(x), __float2half_rn(y));
    return *(uint32_t*)&p;
}
__device__ __forceinline__ void cp_async16(uint32_t saddr, const void* gaddr) {
    asm volatile("cp.async.cg.shared.global [%0], [%1], 16;" :: "r"(saddr), "l"(gaddr));
}
__device__ __forceinline__ void cp_commit() {
    asm volatile("cp.async.commit_group;" ::: "memory");
}
__device__ __forceinline__ void cp_wait0() {
    asm volatile("cp.async.wait_group 0;" ::: "memory");
}
__device__ __forceinline__ void cp_wait1() {
    asm volatile("cp.async.wait_group 1;" ::: "memory");
}

// ---------------------------------------------------------------------------
// Weight prep: fp32 W -> dense fp16
// ---------------------------------------------------------------------------
__global__ void prep_weight(const float* __restrict__ W, __half* __restrict__ out,
                            int total)
{
    int i = blockIdx.x * blockDim.x + threadIdx.x;
    if (i >= total) return;
    out[i] = __float2half_rn(W[i]);
}

// ---------------------------------------------------------------------------
// mma.sync GEMM: C[M,Nd] = op(A)[M,K] @ W[K,Nd] (+bias)
// Single-pass fp16: A = fp16(a), B = fp16(W), fp32 accumulate.
// Validated quadrature model: A-trunc + B-trunc independent -> rel_err ~5.9e-4.
//   BNA:   A transformed relu(a*scale[k]+shift[k]) at staging
//   GATH:  epilogue adds Ph[src[r]] + Ph[dst[r]] + U1[gid[src[r]]]
//   SCAT:  epilogue atomicAdds rows into segout[seg[r]]
//   STATS: per-column sum/sumsq into st_sum/st_sq
// 128x128 tile, 256 threads (8 warps as 4x2; warp tile 32x64), KC=32.
// 2 CTAs/SM; B double-buffered via cp.async (R7-proven loop structure).
// Requires Nd % 128 == 0, K % 32 == 0.
// ---------------------------------------------------------------------------
#define APAD 80     // bytes per A smem row (32 fp16 = 64B + 16B pad)
#define BPAD 272    // bytes per B smem row (128 fp16 = 256B + 16B pad)

template<bool BNA, bool SCAT, bool GATH, bool STATS>
__global__ void __launch_bounds__(256, 2)
gemm_mma(const float* __restrict__ A, const __half* __restrict__ Bp,
         const float* __restrict__ bias, float* __restrict__ C,
         int M, int K, int Nd,
         const float* __restrict__ bnscale, const float* __restrict__ bnshift,
         const int* __restrict__ seg, float* __restrict__ segout,
         const float* __restrict__ Ph, const float* __restrict__ U1,
         const int* __restrict__ src, const int* __restrict__ dst,
         const int* __restrict__ gid,
         float* __restrict__ st_sum, float* __restrict__ st_sq)
{
    __shared__ __align__(16) char sA[128 * APAD];
    __shared__ __align__(16) char sB[2][32 * BPAD];
    __shared__ float ssc[HID];
    __shared__ float ssh[HID];
    __shared__ float ssum[128];
    __shared__ float ssq[128];

    const int tid  = threadIdx.x;
    const int wid  = tid >> 5;
    const int lane = tid & 31;
    const int wm   = wid & 3;     // warp row (32 rows)
    const int wn   = wid >> 2;    // warp col (64 cols)
    const int row0 = blockIdx.y * 128;
    const int col0 = blockIdx.x * 128;

    if (BNA) {
        for (int i = tid; i < K; i += 256) { ssc[i] = bnscale[i]; ssh[i] = bnshift[i]; }
    }
    if (STATS && tid < 128) { ssum[tid] = 0.f; ssq[tid] = 0.f; }

    // ---- staging thread mapping ----
    const int arow = tid >> 1;            // 0..127
    const int acol = (tid & 1) * 16;      // 0 or 16
    const bool avalid = (row0 + arow) < M;
    const float* Ap = A + (size_t)(row0 + arow) * K + acol;

    const int brow = tid >> 3;            // 0..31
    const int bcol = (tid & 7) * 16;      // 0..112

    float acc[2][8][4];
    #pragma unroll
    for (int i = 0; i < 2; i++)
        #pragma unroll
        for (int j = 0; j < 8; j++)
            #pragma unroll
            for (int q = 0; q < 4; q++) acc[i][j][q] = 0.f;

    const uint32_t aB  = smem_u32(sA);
    const uint32_t bB0 = smem_u32(sB[0]);
    const uint32_t bB1 = smem_u32(sB[1]);

    // lane-invariant fragment address parts
    const uint32_t aoff = (uint32_t)((lane & 15) * APAD + (lane >> 4) * 16);
    const uint32_t boff = (uint32_t)((((lane >> 3) & 1) * 8 + (lane & 7)) * BPAD + (lane >> 4) * 16);

    const int nchunk = K >> 5;
    const uint32_t bdst = (uint32_t)(brow * BPAD + bcol * 2);

    // issue B chunk 0 into buffer 0
    cp_async16(bB0 + bdst,      Bp + (size_t)brow * Nd + col0 + bcol);
    cp_async16(bB0 + bdst + 16, Bp + (size_t)brow * Nd + col0 + bcol + 8);
    cp_commit();

    // prefetch A chunk 0 into registers
    float4 aval[4];
    if (avalid) {
        #pragma unroll
        for (int q = 0; q < 4; q++) aval[q] = *(const float4*)(Ap + q * 4);
    } else {
        #pragma unroll
        for (int q = 0; q < 4; q++) aval[q] = make_float4(0.f, 0.f, 0.f, 0.f);
    }
    __syncthreads();   // covers ssc/ssh/ssum init too

    for (int c = 0; c < nchunk; c++) {
        if (c > 0) __syncthreads();
        // ---- store stage (convert A to fp16) ----
        {
            const int kb = c * 32 + acol;
            char* ah = sA + arow * APAD + acol * 2;
            #pragma unroll
            for (int q = 0; q < 4; q++) {
                float4 v = aval[q];
                if (BNA) {
                    const int k = kb + q * 4;
                    v.x = fmaxf(fmaf(v.x, ssc[k + 0], ssh[k + 0]), 0.f);
                    v.y = fmaxf(fmaf(v.y, ssc[k + 1], ssh[k + 1]), 0.f);
                    v.z = fmaxf(fmaf(v.z, ssc[k + 2], ssh[k + 2]), 0.f);
                    v.w = fmaxf(fmaf(v.w, ssc[k + 3], ssh[k + 3]), 0.f);
                }
                uint2 hv;
                hv.x = packh2(v.x, v.y);
                hv.y = packh2(v.z, v.w);
                *(uint2*)(ah + q * 8) = hv;
            }
        }
        // ---- issue next B chunk into the other buffer ----
        if (c + 1 < nchunk) {
            const uint32_t nb = ((c + 1) & 1) ? bB1 : bB0;
            const __half* bp = Bp + (size_t)((c + 1) * 32 + brow) * Nd + col0 + bcol;
            cp_async16(nb + bdst, bp);
            cp_async16(nb + bdst + 16, bp + 8);
            cp_commit();
            cp_wait1();     // B chunk c has landed
        } else {
            cp_wait0();
        }
        __syncthreads();
        // ---- prefetch next A chunk into registers ----
        if (c + 1 < nchunk && avalid) {
            const float* ap = Ap + (c + 1) * 32;
            #pragma unroll
            for (int q = 0; q < 4; q++) aval[q] = *(const float4*)(ap + q * 4);
        }
        // ---- compute on buffer c&1 (single pass) ----
        const uint32_t bBc = (c & 1) ? bB1 : bB0;
        #pragma unroll
        for (int kk = 0; kk < 2; kk++) {
            uint32_t af[2][4], bx[8][2];
            #pragma unroll
            for (int p = 0; p < 4; p++) {
                uint32_t r[4];
                ldsm4t(r, bBc + boff + (uint32_t)(kk * 16 * BPAD + (64 * wn + p * 16) * 2));
                bx[2 * p][0] = r[0]; bx[2 * p][1] = r[1];
                bx[2 * p + 1][0] = r[2]; bx[2 * p + 1][1] = r[3];
            }
            #pragma unroll
            for (int i = 0; i < 2; i++)
                ldsm4(af[i], aB + aoff + (uint32_t)((32 * wm + 16 * i) * APAD + kk * 32));
            #pragma unroll
            for (int i = 0; i < 2; i++)
                #pragma unroll
                for (int j = 0; j < 8; j++)
                    mma16816(acc[i][j], af[i], bx[j][0], bx[j][1]);
        }
        if (c + 1 < nchunk) __syncthreads();   // A smem reusable next iter
    }

    // ---- epilogue ----
    const int m4 = lane >> 2;
    const int n2 = (lane & 3) * 2;

    float bcolv[16];
    #pragma unroll
    for (int j = 0; j < 8; j++) {
        if (bias) {
            float2 b2 = *(const float2*)(bias + col0 + 64 * wn + 8 * j + n2);
            bcolv[2 * j] = b2.x; bcolv[2 * j + 1] = b2.y;
        } else {
            bcolv[2 * j] = 0.f; bcolv[2 * j + 1] = 0.f;
        }
    }
    float csum[16], csq[16];
    if (STATS) {
        #pragma unroll
        for (int q = 0; q < 16; q++) { csum[q] = 0.f; csq[q] = 0.f; }
    }

    #pragma unroll
    for (int i = 0; i < 2; i++) {
        const int rb = row0 + 32 * wm + 16 * i + m4;
        #pragma unroll
        for (int hf = 0; hf < 2; hf++) {
            const int r = rb + 8 * hf;
            if (r >= M) continue;
            int si = 0, di = 0, gi2 = 0, sg = 0;
            if (GATH) { si = src[r]; di = dst[r]; gi2 = gid[si]; }
            if (SCAT) sg = seg[r];
            #pragma unroll
            for (int j = 0; j < 8; j++) {
                const int gc = col0 + 64 * wn + 8 * j + n2;
                float v0 = acc[i][j][2 * hf]     + bcolv[2 * j];
                float v1 = acc[i][j][2 * hf + 1] + bcolv[2 * j + 1];
                if (GATH) {
                    float2 g1 = *(const float2*)(Ph + (size_t)si * HID + gc);
                    float2 g2 = *(const float2*)(Ph + (size_t)di * HID + gc);
                    float2 g3 = *(const float2*)(U1 + (size_t)gi2 * HID + gc);
                    v0 += g1.x + g2.x + g3.x;
                    v1 += g1.y + g2.y + g3.y;
                }
                *(float2*)(C + (size_t)r * Nd + gc) = make_float2(v0, v1);
                if (SCAT) {
                    float* so = segout + (size_t)sg * Nd + gc;
                    atomicAdd(so, v0); atomicAdd(so + 1, v1);
                }
                if (STATS) {
                    csum[2 * j] += v0;     csq[2 * j] += v0 * v0;
                    csum[2 * j + 1] += v1; csq[2 * j + 1] += v1 * v1;
                }
            }
        }
    }
    if (STATS) {
        #pragma unroll
        for (int j = 0; j < 8; j++) {
            const int cl0 = 64 * wn + 8 * j + n2;
            atomicAdd(&ssum[cl0], csum[2 * j]);
            atomicAdd(&ssum[cl0 + 1], csum[2 * j + 1]);
            atomicAdd(&ssq[cl0], csq[2 * j]);
            atomicAdd(&ssq[cl0 + 1], csq[2 * j + 1]);
        }
        __syncthreads();
        if (tid < 128) {
            atomicAdd(&st_sum[col0 + tid], ssum[tid]);
            atomicAdd(&st_sq[col0 + tid], ssq[tid]);
        }
    }
}

// ---------------------------------------------------------------------------
// Elementwise / scatter kernels
// ---------------------------------------------------------------------------
__global__ void zerok(float* __restrict__ p, size_t n) {
    size_t i = (size_t)blockIdx.x * blockDim.x + threadIdx.x;
    size_t st = (size_t)gridDim.x * blockDim.x;
    for (; i < n; i += st) p[i] = 0.f;
}

__global__ void edge_scatter_h(const float* __restrict__ h, const int* __restrict__ src,
                               const int* __restrict__ dst, float* __restrict__ SH, int E)
{
    int idx = blockIdx.x * blockDim.x + threadIdx.x;
    int tot = E * 32;
    if (idx >= tot) return;
    int ei = idx >> 5;
    int c  = (idx & 31) << 2;
    int s = src[ei], d = dst[ei];
    float4 v = *(const float4*)&h[(size_t)s * D + c];
    float* o = SH + (size_t)d * D + c;
    atomicAdd(o + 0, v.x); atomicAdd(o + 1, v.y);
    atomicAdd(o + 2, v.z); atomicAdd(o + 3, v.w);
}

__global__ void bn_prep(float* __restrict__ sum, float* __restrict__ sq,
                        const float* __restrict__ g1, const float* __restrict__ beta1,
                        float* __restrict__ scale, float* __restrict__ shift, float invM)
{
    const int c = threadIdx.x;
    float mean = sum[c] * invM;
    float var  = sq[c] * invM - mean * mean;
    float rstd = rsqrtf(var + 1e-5f);
    float sc = rstd * g1[c];
    scale[c] = sc;
    shift[c] = beta1[c] - mean * sc;
    sum[c] = 0.f;
    sq[c] = 0.f;
}

__global__ void node_build(const float* __restrict__ h, const float* __restrict__ u,
                           const int* __restrict__ gid,
                           const float* __restrict__ SH, const float* __restrict__ SE,
                           float* __restrict__ Xa, float* __restrict__ UE, int N)
{
    int idx = blockIdx.x * blockDim.x + threadIdx.x;
    int tot = N * 32;
    if (idx >= tot) return;
    int n = idx >> 5;
    int c = (idx & 31) << 2;
    int g = gid[n];
    float4 sh = *(const float4*)&SH[(size_t)n * D + c];
    float4 hv = *(const float4*)&h[(size_t)n * D + c];
    float4 se = *(const float4*)&SE[(size_t)n * D + c];
    float4 uv = *(const float4*)&u[(size_t)g * D + c];
    size_t base = (size_t)n * HID;
    *(float4*)&Xa[base + c]         = make_float4(sh.x + hv.x, sh.y + hv.y, sh.z + hv.z, sh.w + hv.w);
    *(float4*)&Xa[base + D + c]     = se;
    *(float4*)&Xa[base + 2 * D + c] = uv;
    float* o = UE + (size_t)g * D + c;
    atomicAdd(o + 0, 0.5f * se.x); atomicAdd(o + 1, 0.5f * se.y);
    atomicAdd(o + 2, 0.5f * se.z); atomicAdd(o + 3, 0.5f * se.w);
}

__global__ void graph_build(const float* __restrict__ u, const float* __restrict__ UH,
                            const float* __restrict__ UE, float* __restrict__ Xg, int G)
{
    int idx = blockIdx.x * blockDim.x + threadIdx.x;
    int tot = G * 32;
    if (idx >= tot) return;
    int g = idx >> 5;
    int c = (idx & 31) << 2;
    size_t base = (size_t)g * HID;
    *(float4*)&Xg[base + c]         = *(const float4*)&UH[(size_t)g * D + c];
    *(float4*)&Xg[base + D + c]     = *(const float4*)&UE[(size_t)g * D + c];
    *(float4*)&Xg[base + 2 * D + c] = *(const float4*)&u[(size_t)g * D + c];
}

// ---------------------------------------------------------------------------
// Dispatch. mode: 0 plain, 1 GATH+STATS, 2 BNA+SCAT, 3 STATS, 4 BNA
// ---------------------------------------------------------------------------
static void run_gemm_mma(int mode,
                         const float* A, const __half* Bp, const float* bias, float* C,
                         int M, int K, int Nd,
                         const float* sc, const float* sh,
                         const int* seg, float* segout,
                         const float* Ph, const float* U1,
                         const int* src, const int* dst, const int* gid,
                         float* st_sum, float* st_sq)
{
    dim3 grid(Nd / 128, (M + 127) / 128);
    switch (mode) {
    case 0: gemm_mma<false,false,false,false><<<grid,256>>>(A,Bp,bias,C,M,K,Nd,sc,sh,seg,segout,Ph,U1,src,dst,gid,st_sum,st_sq); break;
    case 1: gemm_mma<false,false,true, true ><<<grid,256>>>(A,Bp,bias,C,M,K,Nd,sc,sh,seg,segout,Ph,U1,src,dst,gid,st_sum,st_sq); break;
    case 2: gemm_mma<true, true, false,false><<<grid,256>>>(A,Bp,bias,C,M,K,Nd,sc,sh,seg,segout,Ph,U1,src,dst,gid,st_sum,st_sq); break;
    case 3: gemm_mma<false,false,false,true ><<<grid,256>>>(A,Bp,bias,C,M,K,Nd,sc,sh,seg,segout,Ph,U1,src,dst,gid,st_sum,st_sq); break;
    case 4: gemm_mma<true, false,false,false><<<grid,256>>>(A,Bp,bias,C,M,K,Nd,sc,sh,seg,segout,Ph,U1,src,dst,gid,st_sum,st_sq); break;
    }
}

extern "C" void kernel_launch(void* const* d_in, const int* in_sizes, int n_in,
                              void* d_out, int out_size)
{
    const float* h   = (const float*)d_in[0];
    const float* e   = (const float*)d_in[1];
    const float* u   = (const float*)d_in[2];
    const int*   src = (const int*)d_in[3];
    const int*   dst = (const int*)d_in[4];
    const int*   gid = (const int*)d_in[5];

    const float* bW1 = (const float*)d_in[6];
    const float* bb1 = (const float*)d_in[7];
    const float* bg1 = (const float*)d_in[8];
    const float* bbt = (const float*)d_in[9];
    const float* bW2 = (const float*)d_in[10];
    const float* bb2 = (const float*)d_in[11];

    const float* aW1 = (const float*)d_in[12];
    const float* ab1 = (const float*)d_in[13];
    const float* ag1 = (const float*)d_in[14];
    const float* abt = (const float*)d_in[15];
    const float* aW2 = (const float*)d_in[16];
    const float* ab2 = (const float*)d_in[17];

    const float* gW1 = (const float*)d_in[18];
    const float* gb1 = (const float*)d_in[19];
    const float* gg1 = (const float*)d_in[20];
    const float* gbt = (const float*)d_in[21];
    const float* gW2 = (const float*)d_in[22];
    const float* gb2 = (const float*)d_in[23];

    const int N = in_sizes[5];
    const int E = in_sizes[3];
    const int G = in_sizes[2] / D;

    float* scratch = nullptr;
    cudaGetSymbolAddress((void**)&scratch, g_scratch);

    float* Zb = scratch + OFF_ZB;
    float* Ph = scratch + OFF_PH;
    float* U1 = scratch + OFF_U1;
    float* Xa = scratch + OFF_XA;
    float* Za = scratch + OFF_ZA;
    float* Xg = scratch + OFF_XG;
    float* Zg = scratch + OFF_ZG;
    float* SH = scratch + OFF_SH;
    float* SE = scratch + OFF_SE;
    float* UH = scratch + OFF_UH;
    float* UE = scratch + OFF_UE;
    float* st_sum   = scratch + OFF_ST;
    float* st_sq    = st_sum + HID;
    float* bn_scale = st_sq + HID;
    float* bn_shift = bn_scale + HID;
    __half* WP = (__half*)(scratch + OFF_WP);

    float* out_h = (float*)d_out;
    float* out_e = out_h + (size_t)N * D;
    float* out_u = out_e + (size_t)E * D;

    // Zero accumulators (SH, SE, UH, UE, stats) — contiguous region.
    {
        size_t nz = (size_t)MAXN * D * 2 + (size_t)MAXG * D * 2 + 2 * HID;
        zerok<<<2048, 256>>>(SH, nz);
    }

    // Pre-convert all weights to dense fp16.
    {
        const int T1 = 128 * HID, T2 = HID * HID, T3 = HID * D;
        prep_weight<<<(T1 + 255) / 256, 256>>>(bW1,                       WP + WPO_BW1A, T1);
        prep_weight<<<(T1 + 255) / 256, 256>>>(bW1 + (size_t)D * HID,     WP + WPO_BW1B, T1);
        prep_weight<<<(T1 + 255) / 256, 256>>>(bW1 + (size_t)2 * D * HID, WP + WPO_BW1C, T1);
        prep_weight<<<(T3 + 255) / 256, 256>>>(bW2, WP + WPO_BW2, T3);
        prep_weight<<<(T2 + 255) / 256, 256>>>(aW1, WP + WPO_AW1, T2);
        prep_weight<<<(T3 + 255) / 256, 256>>>(aW2, WP + WPO_AW2, T3);
        prep_weight<<<(T2 + 255) / 256, 256>>>(gW1, WP + WPO_GW1, T2);
        prep_weight<<<(T3 + 255) / 256, 256>>>(gW2, WP + WPO_GW2, T3);
    }

    // ---- Bond path ----
    run_gemm_mma(0, h, WP + WPO_BW1A, nullptr, Ph, N, 128, HID,
                 nullptr, nullptr, nullptr, nullptr, nullptr, nullptr, nullptr, nullptr, nullptr, nullptr, nullptr);
    run_gemm_mma(0, u, WP + WPO_BW1C, bb1, U1, G, 128, HID,
                 nullptr, nullptr, nullptr, nullptr, nullptr, nullptr, nullptr, nullptr, nullptr, nullptr, nullptr);
    edge_scatter_h<<<(E * 32 + 255) / 256, 256>>>(h, src, dst, SH, E);
    // Zb = e@bW1b + Ph[src] + Ph[dst] + U1[gid[src]]; fused stats
    run_gemm_mma(1, e, WP + WPO_BW1B, nullptr, Zb, E, 128, HID,
                 nullptr, nullptr, nullptr, nullptr, Ph, U1, src, dst, gid, st_sum, st_sq);
    bn_prep<<<1, HID>>>(st_sum, st_sq, bg1, bbt, bn_scale, bn_shift, 1.f / (float)E);
    // e_new = relu(BN(Zb)) @ bW2 + bb2 ; SE[dst] += e_new
    run_gemm_mma(2, Zb, WP + WPO_BW2, bb2, out_e, E, HID, D,
                 bn_scale, bn_shift, dst, SE, nullptr, nullptr, nullptr, nullptr, nullptr, nullptr, nullptr);

    // ---- Atom path ----
    node_build<<<(N * 32 + 255) / 256, 256>>>(h, u, gid, SH, SE, Xa, UE, N);
    run_gemm_mma(3, Xa, WP + WPO_AW1, ab1, Za, N, HID, HID,
                 nullptr, nullptr, nullptr, nullptr, nullptr, nullptr, nullptr, nullptr, nullptr, st_sum, st_sq);
    bn_prep<<<1, HID>>>(st_sum, st_sq, ag1, abt, bn_scale, bn_shift, 1.f / (float)N);
    run_gemm_mma(2, Za, WP + WPO_AW2, ab2, out_h, N, HID, D,
                 bn_scale, bn_shift, gid, UH, nullptr, nullptr, nullptr, nullptr, nullptr, nullptr, nullptr);

    // ---- Global path ----
    graph_build<<<(G * 32 + 255) / 256, 256>>>(u, UH, UE, Xg, G);
    run_gemm_mma(3, Xg, WP + WPO_GW1, gb1, Zg, G, HID, HID,
                 nullptr, nullptr, nullptr, nullptr, nullptr, nullptr, nullptr, nullptr, nullptr, st_sum, st_sq);
    bn_prep<<<1, HID>>>(st_sum, st_sq, gg1, gbt, bn_scale, bn_shift, 1.f / (float)G);
    run_gemm_mma(4, Zg, WP + WPO_GW2, gb2, out_u, G, HID, D,
                 bn_scale, bn_shift, nullptr, nullptr, nullptr, nullptr, nullptr, nullptr, nullptr, nullptr, nullptr);
}

// round 11
// speedup vs baseline: 1.1432x; 1.0142x over previous
#include <cuda_runtime.h>
#include <cuda_fp16.h>
#include <cstdint>
#include <cstddef>

#define D 128
#define HID 384
#define MAXN 100000
#define MAXE 500000
#define MAXG 5000

// ---------------------------------------------------------------------------
// Scratch layout (floats)
// ---------------------------------------------------------------------------
static const size_t OFF_ZB = 0;                                    // E*384
static const size_t OFF_PH = OFF_ZB + (size_t)MAXE * HID;          // N*384
static const size_t OFF_U1 = OFF_PH + (size_t)MAXN * HID;          // G*384
static const size_t OFF_ZA = OFF_U1 + (size_t)MAXG * HID;          // N*384
static const size_t OFF_ZG = OFF_ZA + (size_t)MAXN * HID;          // G*384
static const size_t OFF_SH = OFF_ZG + (size_t)MAXG * HID;          // N*128
static const size_t OFF_SE = OFF_SH + (size_t)MAXN * D;            // N*128
static const size_t OFF_UH = OFF_SE + (size_t)MAXN * D;            // G*128
static const size_t OFF_UE = OFF_UH + (size_t)MAXG * D;            // G*128
static const size_t OFF_ST = OFF_UE + (size_t)MAXG * D;            // 4*384
static const size_t OFF_WP   = OFF_ST + 4 * HID;                   // 589824 halves
static const size_t OFF_XA16 = OFF_WP + 294912;                    // N*384 halves
static const size_t OFF_XG16 = OFF_XA16 + (size_t)MAXN * HID / 2;  // G*384 halves
static const size_t OFF_E16  = OFF_XG16 + (size_t)MAXG * HID / 2;  // E*128 halves
static const size_t OFF_H16  = OFF_E16 + (size_t)MAXE * D / 2;     // N*128 halves
static const size_t OFF_U16  = OFF_H16 + (size_t)MAXN * D / 2;     // G*128 halves
static const size_t TOTAL_SCRATCH = OFF_U16 + (size_t)MAXG * D / 2 + 1024;

__device__ __align__(256) float g_scratch[TOTAL_SCRATCH];

// Prepped-weight offsets in half elements (dense fp16).
#define WPO_BW1A 0
#define WPO_BW1B 49152
#define WPO_BW1C 98304
#define WPO_BW2  147456
#define WPO_AW1  196608
#define WPO_AW2  344064
#define WPO_GW1  393216
#define WPO_GW2  540672

// ---------------------------------------------------------------------------
// PTX helpers (arch-agnostic: ldmatrix sm_75+, fp16 mma sm_80+, cp.async sm_80+)
// ---------------------------------------------------------------------------
__device__ __forceinline__ uint32_t smem_u32(const void* p) {
    uint32_t a;
    asm("{ .reg .u64 t; cvta.to.shared.u64 t, %1; cvt.u32.u64 %0, t; }" : "=r"(a) : "l"(p));
    return a;
}
__device__ __forceinline__ void ldsm4(uint32_t (&r)[4], uint32_t addr) {
    asm volatile("ldmatrix.sync.aligned.m8n8.x4.shared.b16 {%0,%1,%2,%3}, [%4];"
                 : "=r"(r[0]), "=r"(r[1]), "=r"(r[2]), "=r"(r[3]) : "r"(addr));
}
__device__ __forceinline__ void ldsm4t(uint32_t (&r)[4], uint32_t addr) {
    asm volatile("ldmatrix.sync.aligned.m8n8.x4.trans.shared.b16 {%0,%1,%2,%3}, [%4];"
                 : "=r"(r[0]), "=r"(r[1]), "=r"(r[2]), "=r"(r[3]) : "r"(addr));
}
__device__ __forceinline__ void mma16816(float (&c)[4], const uint32_t (&a)[4],
                                         uint32_t b0, uint32_t b1) {
    asm volatile(
        "mma.sync.aligned.m16n8k16.row.col.f32.f16.f16.f32 "
        "{%0,%1,%2,%3}, {%4,%5,%6,%7}, {%8,%9}, {%0,%1,%2,%3};"
        : "+f"(c[0]), "+f"(c[1]), "+f"(c[2]), "+f"(c[3])
        : "r"(a[0]), "r"(a[1]), "r"(a[2]), "r"(a[3]), "r"(b0), "r"(b1));
}
__device__ __forceinline__ uint32_t packh2(float x, float y) {
    __half2 p = __halves2half2(__float2half_rn(x), __float2half_rn(y));
    return *(uint32_t*)&p;
}
__device__ __forceinline__ void cp_async16(uint32_t saddr, const void* gaddr) {
    asm volatile("cp.async.cg.shared.global [%0], [%1], 16;" :: "r"(saddr), "l"(gaddr));
}
// zfill variant: src-size 0 reads nothing and fills with zeros (ragged rows)
__device__ __forceinline__ void cp_async16z(uint32_t saddr, const void* gaddr, bool valid) {
    int sz = valid ? 16 : 0;
    asm volatile("cp.async.cg.shared.global [%0], [%1], 16, %2;"
                 :: "r"(saddr), "l"(gaddr), "r"(sz));
}
__device__ __forceinline__ void cp_commit() {
    asm volatile("cp.async.commit_group;" ::: "memory");
}
__device__ __forceinline__ void cp_wait0() {
    asm volatile("cp.async.wait_group 0;" ::: "memory");
}
__device__ __forceinline__ void cp_wait1() {
    asm volatile("cp.async.wait_group 1;" ::: "memory");
}

// ---------------------------------------------------------------------------
// prep kernels: fp32 -> fp16 (dense) — same truncation the GEMM staging did
// ---------------------------------------------------------------------------
__global__ void prep_weight(const float* __restrict__ W, __half* __restrict__ out,
                            int total)
{
    int i = blockIdx.x * blockDim.x + threadIdx.x;
    if (i >= total) return;
    out[i] = __float2half_rn(W[i]);
}
__global__ void cvt_half4(const float* __restrict__ in, __half* __restrict__ out, int n4)
{
    int i = blockIdx.x * blockDim.x + threadIdx.x;
    if (i >= n4) return;
    float4 v = ((const float4*)in)[i];
    uint2 w;
    w.x = packh2(v.x, v.y);
    w.y = packh2(v.z, v.w);
    ((uint2*)out)[i] = w;
}

// ---------------------------------------------------------------------------
// mma.sync GEMM: C[M,Nd] = op(A)[M,K] @ W[K,Nd] (+bias), fp32 accumulate.
//  HALFA: A already fp16 in gmem -> staged via cp.async (no convert chain)
//  !HALFA: A fp32, converted to fp16 in staging (BNA applies relu(a*sc+sh))
//  GATH:  epilogue adds Ph[src[r]] + Ph[dst[r]] + U1[gid[src[r]]]
//  SCAT:  epilogue atomicAdds rows into segout[seg[r]]
//  STATS: per-column sum/sumsq into st_sum/st_sq
//  HSCAT: (col0==0 CTAs) SH[dst[r]] += h[src[r]]  (fused edge_scatter)
// 128x128 tile, 256 threads (8 warps 4x2, warp tile 32x64), KC=32, 2 CTAs/SM.
// Requires Nd % 128 == 0, K % 32 == 0.
// ---------------------------------------------------------------------------
#define APAD 80     // bytes per A smem row (32 fp16 = 64B + 16B pad)
#define BPAD 272    // bytes per B smem row (128 fp16 = 256B + 16B pad)

template<bool HALFA, bool BNA, bool SCAT, bool GATH, bool STATS, bool HSCAT>
__global__ void __launch_bounds__(256, 2)
gemm_mma(const void* __restrict__ Avoid, const __half* __restrict__ Bp,
         const float* __restrict__ bias, float* __restrict__ C,
         int M, int K, int Nd,
         const float* __restrict__ bnscale, const float* __restrict__ bnshift,
         const int* __restrict__ seg, float* __restrict__ segout,
         const float* __restrict__ Ph, const float* __restrict__ U1,
         const int* __restrict__ src, const int* __restrict__ dst,
         const int* __restrict__ gid,
         float* __restrict__ st_sum, float* __restrict__ st_sq,
         const float* __restrict__ Hg, float* __restrict__ SHg)
{
    __shared__ __align__(16) char sA[2][128 * APAD];
    __shared__ __align__(16) char sB[2][32 * BPAD];
    __shared__ float ssc[HID];
    __shared__ float ssh[HID];
    __shared__ float ssum[128];
    __shared__ float ssq[128];

    const int tid  = threadIdx.x;
    const int wid  = tid >> 5;
    const int lane = tid & 31;
    const int wm   = wid & 3;     // warp row (32 rows)
    const int wn   = wid >> 2;    // warp col (64 cols)
    const int row0 = blockIdx.y * 128;
    const int col0 = blockIdx.x * 128;

    if (BNA) {
        for (int i = tid; i < K; i += 256) { ssc[i] = bnscale[i]; ssh[i] = bnshift[i]; }
    }
    if (STATS && tid < 128) { ssum[tid] = 0.f; ssq[tid] = 0.f; }

    // ---- staging thread mapping ----
    const int arow = tid >> 1;            // 0..127
    const int acol = (tid & 1) * 16;      // element offset (16 elems/thread)
    const bool avalid = (row0 + arow) < M;
    const float*  Af = (const float*) Avoid + (size_t)(row0 + arow) * K + acol;
    const __half* Ah = (const __half*)Avoid + (size_t)(row0 + arow) * K + acol;

    const int brow = tid >> 3;            // 0..31
    const int bcol = (tid & 7) * 16;      // 0..112

    float acc[2][8][4];
    #pragma unroll
    for (int i = 0; i < 2; i++)
        #pragma unroll
        for (int j = 0; j < 8; j++)
            #pragma unroll
            for (int q = 0; q < 4; q++) acc[i][j][q] = 0.f;

    const uint32_t aB0 = smem_u32(sA[0]);
    const uint32_t aB1 = smem_u32(sA[1]);
    const uint32_t bB0 = smem_u32(sB[0]);
    const uint32_t bB1 = smem_u32(sB[1]);

    const uint32_t aoff = (uint32_t)((lane & 15) * APAD + (lane >> 4) * 16);
    const uint32_t boff = (uint32_t)((((lane >> 3) & 1) * 8 + (lane & 7)) * BPAD + (lane >> 4) * 16);

    const int nchunk = K >> 5;
    const uint32_t bdst = (uint32_t)(brow * BPAD + bcol * 2);
    const uint32_t adst = (uint32_t)(arow * APAD + acol * 2);

    float4 aval[4];   // fp32 path register prefetch

    if (HALFA) {
        // prologue: A0 + B0 as one cp.async group
        cp_async16z(aB0 + adst,      Ah,     avalid);
        cp_async16z(aB0 + adst + 16, Ah + 8, avalid);
        cp_async16(bB0 + bdst,      Bp + (size_t)brow * Nd + col0 + bcol);
        cp_async16(bB0 + bdst + 16, Bp + (size_t)brow * Nd + col0 + bcol + 8);
        cp_commit();
    } else {
        cp_async16(bB0 + bdst,      Bp + (size_t)brow * Nd + col0 + bcol);
        cp_async16(bB0 + bdst + 16, Bp + (size_t)brow * Nd + col0 + bcol + 8);
        cp_commit();
        if (avalid) {
            #pragma unroll
            for (int q = 0; q < 4; q++) aval[q] = *(const float4*)(Af + q * 4);
        } else {
            #pragma unroll
            for (int q = 0; q < 4; q++) aval[q] = make_float4(0.f, 0.f, 0.f, 0.f);
        }
    }
    __syncthreads();   // covers ssc/ssh/ssum init too

    for (int c = 0; c < nchunk; c++) {
        const int buf = c & 1;
        if (HALFA) {
            // issue A+B for chunk c+1 into the other buffer.
            // Safe: buffer buf^1 was last read in compute(c-1), which is
            // ordered before this point by the trailing sync of iter c-1.
            if (c + 1 < nchunk) {
                const uint32_t na = (buf ^ 1) ? aB1 : aB0;
                const uint32_t nb = (buf ^ 1) ? bB1 : bB0;
                cp_async16z(na + adst,      Ah + (c + 1) * 32,     avalid);
                cp_async16z(na + adst + 16, Ah + (c + 1) * 32 + 8, avalid);
                const __half* bp = Bp + (size_t)((c + 1) * 32 + brow) * Nd + col0 + bcol;
                cp_async16(nb + bdst, bp);
                cp_async16(nb + bdst + 16, bp + 8);
                cp_commit();
                cp_wait1();     // group for chunk c has landed
            } else {
                cp_wait0();
            }
            __syncthreads();
        } else {
            if (c > 0) __syncthreads();
            // ---- store stage (convert A to fp16, BN applied) ----
            {
                const int kb = c * 32 + acol;
                char* ah = sA[0] + adst;
                #pragma unroll
                for (int q = 0; q < 4; q++) {
                    float4 v = aval[q];
                    if (BNA) {
                        const int k = kb + q * 4;
                        v.x = fmaxf(fmaf(v.x, ssc[k + 0], ssh[k + 0]), 0.f);
                        v.y = fmaxf(fmaf(v.y, ssc[k + 1], ssh[k + 1]), 0.f);
                        v.z = fmaxf(fmaf(v.z, ssc[k + 2], ssh[k + 2]), 0.f);
                        v.w = fmaxf(fmaf(v.w, ssc[k + 3], ssh[k + 3]), 0.f);
                    }
                    uint2 hv;
                    hv.x = packh2(v.x, v.y);
                    hv.y = packh2(v.z, v.w);
                    *(uint2*)(ah + q * 8) = hv;
                }
            }
            // ---- issue next B chunk into the other buffer ----
            if (c + 1 < nchunk) {
                const uint32_t nb = (buf ^ 1) ? bB1 : bB0;
                const __half* bp = Bp + (size_t)((c + 1) * 32 + brow) * Nd + col0 + bcol;
                cp_async16(nb + bdst, bp);
                cp_async16(nb + bdst + 16, bp + 8);
                cp_commit();
                cp_wait1();
            } else {
                cp_wait0();
            }
            __syncthreads();
            // ---- prefetch next A chunk into registers ----
            if (c + 1 < nchunk && avalid) {
                const float* ap = Af + (c + 1) * 32;
                #pragma unroll
                for (int q = 0; q < 4; q++) aval[q] = *(const float4*)(ap + q * 4);
            }
        }
        // ---- compute chunk c ----
        const uint32_t aBc = HALFA ? (buf ? aB1 : aB0) : aB0;
        const uint32_t bBc = buf ? bB1 : bB0;
        #pragma unroll
        for (int kk = 0; kk < 2; kk++) {
            uint32_t af[2][4], bx[8][2];
            #pragma unroll
            for (int p = 0; p < 4; p++) {
                uint32_t r[4];
                ldsm4t(r, bBc + boff + (uint32_t)(kk * 16 * BPAD + (64 * wn + p * 16) * 2));
                bx[2 * p][0] = r[0]; bx[2 * p][1] = r[1];
                bx[2 * p + 1][0] = r[2]; bx[2 * p + 1][1] = r[3];
            }
            #pragma unroll
            for (int i = 0; i < 2; i++)
                ldsm4(af[i], aBc + aoff + (uint32_t)((32 * wm + 16 * i) * APAD + kk * 32));
            #pragma unroll
            for (int i = 0; i < 2; i++)
                #pragma unroll
                for (int j = 0; j < 8; j++)
                    mma16816(acc[i][j], af[i], bx[j][0], bx[j][1]);
        }
        if (c + 1 < nchunk) __syncthreads();   // guard buffer reuse
    }

    // ---- epilogue ----
    const int m4 = lane >> 2;
    const int n2 = (lane & 3) * 2;
    const bool do_hscat = HSCAT && (col0 == 0);

    float bcolv[16];
    #pragma unroll
    for (int j = 0; j < 8; j++) {
        if (bias) {
            float2 b2 = *(const float2*)(bias + col0 + 64 * wn + 8 * j + n2);
            bcolv[2 * j] = b2.x; bcolv[2 * j + 1] = b2.y;
        } else {
            bcolv[2 * j] = 0.f; bcolv[2 * j + 1] = 0.f;
        }
    }
    float csum[16], csq[16];
    if (STATS) {
        #pragma unroll
        for (int q = 0; q < 16; q++) { csum[q] = 0.f; csq[q] = 0.f; }
    }

    #pragma unroll
    for (int i = 0; i < 2; i++) {
        const int rb = row0 + 32 * wm + 16 * i + m4;
        #pragma unroll
        for (int hf = 0; hf < 2; hf++) {
            const int r = rb + 8 * hf;
            if (r >= M) continue;
            int si = 0, di = 0, gi2 = 0, sg = 0;
            if (GATH) { si = src[r]; di = dst[r]; gi2 = gid[si]; }
            if (SCAT) sg = seg[r];
            #pragma unroll
            for (int j = 0; j < 8; j++) {
                const int gc = col0 + 64 * wn + 8 * j + n2;
                float v0 = acc[i][j][2 * hf]     + bcolv[2 * j];
                float v1 = acc[i][j][2 * hf + 1] + bcolv[2 * j + 1];
                if (GATH) {
                    float2 g1 = *(const float2*)(Ph + (size_t)si * HID + gc);
                    float2 g2 = *(const float2*)(Ph + (size_t)di * HID + gc);
                    float2 g3 = *(const float2*)(U1 + (size_t)gi2 * HID + gc);
                    v0 += g1.x + g2.x + g3.x;
                    v1 += g1.y + g2.y + g3.y;
                }
                *(float2*)(C + (size_t)r * Nd + gc) = make_float2(v0, v1);
                if (SCAT) {
                    float* so = segout + (size_t)sg * Nd + gc;
                    atomicAdd(so, v0); atomicAdd(so + 1, v1);
                }
                if (do_hscat) {
                    // gc < 128 here since col0 == 0 and warp cols < 128
                    float2 hv2 = *(const float2*)(Hg + (size_t)si * D + gc);
                    float* so2 = SHg + (size_t)di * D + gc;
                    atomicAdd(so2, hv2.x); atomicAdd(so2 + 1, hv2.y);
                }
                if (STATS) {
                    csum[2 * j] += v0;     csq[2 * j] += v0 * v0;
                    csum[2 * j + 1] += v1; csq[2 * j + 1] += v1 * v1;
                }
            }
        }
    }
    if (STATS) {
        #pragma unroll
        for (int j = 0; j < 8; j++) {
            const int cl0 = 64 * wn + 8 * j + n2;
            atomicAdd(&ssum[cl0], csum[2 * j]);
            atomicAdd(&ssum[cl0 + 1], csum[2 * j + 1]);
            atomicAdd(&ssq[cl0], csq[2 * j]);
            atomicAdd(&ssq[cl0 + 1], csq[2 * j + 1]);
        }
        __syncthreads();
        if (tid < 128) {
            atomicAdd(&st_sum[col0 + tid], ssum[tid]);
            atomicAdd(&st_sq[col0 + tid], ssq[tid]);
        }
    }
}

// ---------------------------------------------------------------------------
// Elementwise kernels
// ---------------------------------------------------------------------------
__global__ void zerok(float* __restrict__ p, size_t n) {
    size_t i = (size_t)blockIdx.x * blockDim.x + threadIdx.x;
    size_t st = (size_t)gridDim.x * blockDim.x;
    for (; i < n; i += st) p[i] = 0.f;
}

__global__ void bn_prep(float* __restrict__ sum, float* __restrict__ sq,
                        const float* __restrict__ g1, const float* __restrict__ beta1,
                        float* __restrict__ scale, float* __restrict__ shift, float invM)
{
    const int c = threadIdx.x;
    float mean = sum[c] * invM;
    float var  = sq[c] * invM - mean * mean;
    float rstd = rsqrtf(var + 1e-5f);
    float sc = rstd * g1[c];
    scale[c] = sc;
    shift[c] = beta1[c] - mean * sc;
    sum[c] = 0.f;
    sq[c] = 0.f;
}

// Xa16[n] = fp16([SH[n]+h[n], SE[n], u[gid[n]]]); UE[gid[n]] += 0.5*SE[n]
__global__ void node_build(const float* __restrict__ h, const float* __restrict__ u,
                           const int* __restrict__ gid,
                           const float* __restrict__ SH, const float* __restrict__ SE,
                           __half* __restrict__ Xa16, float* __restrict__ UE, int N)
{
    int idx = blockIdx.x * blockDim.x + threadIdx.x;
    int tot = N * 32;
    if (idx >= tot) return;
    int n = idx >> 5;
    int c = (idx & 31) << 2;
    int g = gid[n];
    float4 sh = *(const float4*)&SH[(size_t)n * D + c];
    float4 hv = *(const float4*)&h[(size_t)n * D + c];
    float4 se = *(const float4*)&SE[(size_t)n * D + c];
    float4 uv = *(const float4*)&u[(size_t)g * D + c];
    size_t base = (size_t)n * HID;
    uint2 w;
    w.x = packh2(sh.x + hv.x, sh.y + hv.y);
    w.y = packh2(sh.z + hv.z, sh.w + hv.w);
    *(uint2*)&Xa16[base + c] = w;
    w.x = packh2(se.x, se.y);
    w.y = packh2(se.z, se.w);
    *(uint2*)&Xa16[base + D + c] = w;
    w.x = packh2(uv.x, uv.y);
    w.y = packh2(uv.z, uv.w);
    *(uint2*)&Xa16[base + 2 * D + c] = w;
    float* o = UE + (size_t)g * D + c;
    atomicAdd(o + 0, 0.5f * se.x); atomicAdd(o + 1, 0.5f * se.y);
    atomicAdd(o + 2, 0.5f * se.z); atomicAdd(o + 3, 0.5f * se.w);
}

// Xg16[g] = fp16([UH[g], UE[g], u[g]])
__global__ void graph_build(const float* __restrict__ u, const float* __restrict__ UH,
                            const float* __restrict__ UE, __half* __restrict__ Xg16, int G)
{
    int idx = blockIdx.x * blockDim.x + threadIdx.x;
    int tot = G * 32;
    if (idx >= tot) return;
    int g = idx >> 5;
    int c = (idx & 31) << 2;
    size_t base = (size_t)g * HID;
    float4 a = *(const float4*)&UH[(size_t)g * D + c];
    float4 b = *(const float4*)&UE[(size_t)g * D + c];
    float4 d = *(const float4*)&u[(size_t)g * D + c];
    uint2 w;
    w.x = packh2(a.x, a.y); w.y = packh2(a.z, a.w);
    *(uint2*)&Xg16[base + c] = w;
    w.x = packh2(b.x, b.y); w.y = packh2(b.z, b.w);
    *(uint2*)&Xg16[base + D + c] = w;
    w.x = packh2(d.x, d.y); w.y = packh2(d.z, d.w);
    *(uint2*)&Xg16[base + 2 * D + c] = w;
}

// ---------------------------------------------------------------------------
// Dispatch.
// mode 0: HALFA plain        mode 1: HALFA GATH+STATS+HSCAT
// mode 2: fp32 BNA+SCAT      mode 3: HALFA STATS      mode 4: fp32 BNA
// ---------------------------------------------------------------------------
static void run_gemm_mma(int mode,
                         const void* A, const __half* Bp, const float* bias, float* C,
                         int M, int K, int Nd,
                         const float* sc, const float* sh,
                         const int* seg, float* segout,
                         const float* Ph, const float* U1,
                         const int* src, const int* dst, const int* gid,
                         float* st_sum, float* st_sq,
                         const float* Hg, float* SHg)
{
    dim3 grid(Nd / 128, (M + 127) / 128);
    switch (mode) {
    case 0: gemm_mma<true ,false,false,false,false,false><<<grid,256>>>(A,Bp,bias,C,M,K,Nd,sc,sh,seg,segout,Ph,U1,src,dst,gid,st_sum,st_sq,Hg,SHg); break;
    case 1: gemm_mma<true ,false,false,true ,true ,true ><<<grid,256>>>(A,Bp,bias,C,M,K,Nd,sc,sh,seg,segout,Ph,U1,src,dst,gid,st_sum,st_sq,Hg,SHg); break;
    case 2: gemm_mma<false,true ,true ,false,false,false><<<grid,256>>>(A,Bp,bias,C,M,K,Nd,sc,sh,seg,segout,Ph,U1,src,dst,gid,st_sum,st_sq,Hg,SHg); break;
    case 3: gemm_mma<true ,false,false,false,true ,false><<<grid,256>>>(A,Bp,bias,C,M,K,Nd,sc,sh,seg,segout,Ph,U1,src,dst,gid,st_sum,st_sq,Hg,SHg); break;
    case 4: gemm_mma<false,true ,false,false,false,false><<<grid,256>>>(A,Bp,bias,C,M,K,Nd,sc,sh,seg,segout,Ph,U1,src,dst,gid,st_sum,st_sq,Hg,SHg); break;
    }
}

extern "C" void kernel_launch(void* const* d_in, const int* in_sizes, int n_in,
                              void* d_out, int out_size)
{
    const float* h   = (const float*)d_in[0];
    const float* e   = (const float*)d_in[1];
    const float* u   = (const float*)d_in[2];
    const int*   src = (const int*)d_in[3];
    const int*   dst = (const int*)d_in[4];
    const int*   gid = (const int*)d_in[5];

    const float* bW1 = (const float*)d_in[6];
    const float* bb1 = (const float*)d_in[7];
    const float* bg1 = (const float*)d_in[8];
    const float* bbt = (const float*)d_in[9];
    const float* bW2 = (const float*)d_in[10];
    const float* bb2 = (const float*)d_in[11];

    const float* aW1 = (const float*)d_in[12];
    const float* ab1 = (const float*)d_in[13];
    const float* ag1 = (const float*)d_in[14];
    const float* abt = (const float*)d_in[15];
    const float* aW2 = (const float*)d_in[16];
    const float* ab2 = (const float*)d_in[17];

    const float* gW1 = (const float*)d_in[18];
    const float* gb1 = (const float*)d_in[19];
    const float* gg1 = (const float*)d_in[20];
    const float* gbt = (const float*)d_in[21];
    const float* gW2 = (const float*)d_in[22];
    const float* gb2 = (const float*)d_in[23];

    const int N = in_sizes[5];
    const int E = in_sizes[3];
    const int G = in_sizes[2] / D;

    float* scratch = nullptr;
    cudaGetSymbolAddress((void**)&scratch, g_scratch);

    float* Zb = scratch + OFF_ZB;
    float* Ph = scratch + OFF_PH;
    float* U1 = scratch + OFF_U1;
    float* Za = scratch + OFF_ZA;
    float* Zg = scratch + OFF_ZG;
    float* SH = scratch + OFF_SH;
    float* SE = scratch + OFF_SE;
    float* UH = scratch + OFF_UH;
    float* UE = scratch + OFF_UE;
    float* st_sum   = scratch + OFF_ST;
    float* st_sq    = st_sum + HID;
    float* bn_scale = st_sq + HID;
    float* bn_shift = bn_scale + HID;
    __half* WP   = (__half*)(scratch + OFF_WP);
    __half* Xa16 = (__half*)(scratch + OFF_XA16);
    __half* Xg16 = (__half*)(scratch + OFF_XG16);
    __half* e16  = (__half*)(scratch + OFF_E16);
    __half* h16  = (__half*)(scratch + OFF_H16);
    __half* u16  = (__half*)(scratch + OFF_U16);

    float* out_h = (float*)d_out;
    float* out_e = out_h + (size_t)N * D;
    float* out_u = out_e + (size_t)E * D;

    // Zero accumulators (SH, SE, UH, UE, stats) — contiguous region.
    {
        size_t nz = (size_t)MAXN * D * 2 + (size_t)MAXG * D * 2 + 2 * HID;
        zerok<<<2048, 256>>>(SH, nz);
    }

    // Pre-convert inputs + weights to fp16 (identical truncation to staging).
    {
        cvt_half4<<<(E * D / 4 + 255) / 256, 256>>>(e, e16, E * D / 4);
        cvt_half4<<<(N * D / 4 + 255) / 256, 256>>>(h, h16, N * D / 4);
        cvt_half4<<<(G * D / 4 + 255) / 256, 256>>>(u, u16, G * D / 4);
        const int T1 = 128 * HID, T2 = HID * HID, T3 = HID * D;
        prep_weight<<<(T1 + 255) / 256, 256>>>(bW1,                       WP + WPO_BW1A, T1);
        prep_weight<<<(T1 + 255) / 256, 256>>>(bW1 + (size_t)D * HID,     WP + WPO_BW1B, T1);
        prep_weight<<<(T1 + 255) / 256, 256>>>(bW1 + (size_t)2 * D * HID, WP + WPO_BW1C, T1);
        prep_weight<<<(T3 + 255) / 256, 256>>>(bW2, WP + WPO_BW2, T3);
        prep_weight<<<(T2 + 255) / 256, 256>>>(aW1, WP + WPO_AW1, T2);
        prep_weight<<<(T3 + 255) / 256, 256>>>(aW2, WP + WPO_AW2, T3);
        prep_weight<<<(T2 + 255) / 256, 256>>>(gW1, WP + WPO_GW1, T2);
        prep_weight<<<(T3 + 255) / 256, 256>>>(gW2, WP + WPO_GW2, T3);
    }

    // ---- Bond path ----
    run_gemm_mma(0, h16, WP + WPO_BW1A, nullptr, Ph, N, 128, HID,
                 nullptr, nullptr, nullptr, nullptr, nullptr, nullptr, nullptr, nullptr, nullptr,
                 nullptr, nullptr, nullptr, nullptr);
    run_gemm_mma(0, u16, WP + WPO_BW1C, bb1, U1, G, 128, HID,
                 nullptr, nullptr, nullptr, nullptr, nullptr, nullptr, nullptr, nullptr, nullptr,
                 nullptr, nullptr, nullptr, nullptr);
    // Zb = e@bW1b + Ph[src] + Ph[dst] + U1[gid[src]]; fused stats + SH scatter
    run_gemm_mma(1, e16, WP + WPO_BW1B, nullptr, Zb, E, 128, HID,
                 nullptr, nullptr, nullptr, nullptr, Ph, U1, src, dst, gid, st_sum, st_sq,
                 h, SH);
    bn_prep<<<1, HID>>>(st_sum, st_sq, bg1, bbt, bn_scale, bn_shift, 1.f / (float)E);
    // e_new = relu(BN(Zb)) @ bW2 + bb2 ; SE[dst] += e_new
    run_gemm_mma(2, Zb, WP + WPO_BW2, bb2, out_e, E, HID, D,
                 bn_scale, bn_shift, dst, SE, nullptr, nullptr, nullptr, nullptr, nullptr,
                 nullptr, nullptr, nullptr, nullptr);

    // ---- Atom path ----
    node_build<<<(N * 32 + 255) / 256, 256>>>(h, u, gid, SH, SE, Xa16, UE, N);
    run_gemm_mma(3, Xa16, WP + WPO_AW1, ab1, Za, N, HID, HID,
                 nullptr, nullptr, nullptr, nullptr, nullptr, nullptr, nullptr, nullptr, nullptr,
                 st_sum, st_sq, nullptr, nullptr);
    bn_prep<<<1, HID>>>(st_sum, st_sq, ag1, abt, bn_scale, bn_shift, 1.f / (float)N);
    // h_new = relu(BN(Za)) @ aW2 + ab2 ; UH[gid] += h_new
    run_gemm_mma(2, Za, WP + WPO_AW2, ab2, out_h, N, HID, D,
                 bn_scale, bn_shift, gid, UH, nullptr, nullptr, nullptr, nullptr, nullptr,
                 nullptr, nullptr, nullptr, nullptr);

    // ---- Global path ----
    graph_build<<<(G * 32 + 255) / 256, 256>>>(u, UH, UE, Xg16, G);
    run_gemm_mma(3, Xg16, WP + WPO_GW1, gb1, Zg, G, HID, HID,
                 nullptr, nullptr, nullptr, nullptr, nullptr, nullptr, nullptr, nullptr, nullptr,
                 st_sum, st_sq, nullptr, nullptr);
    bn_prep<<<1, HID>>>(st_sum, st_sq, gg1, gbt, bn_scale, bn_shift, 1.f / (float)G);
    run_gemm_mma(4, Zg, WP + WPO_GW2, gb2, out_u, G, HID, D,
                 bn_scale, bn_shift, nullptr, nullptr, nullptr, nullptr, nullptr, nullptr, nullptr,
                 nullptr, nullptr, nullptr, nullptr);
}

// round 13
// speedup vs baseline: 1.1668x; 1.0206x over previous
#include <cuda_runtime.h>
#include <cuda_fp16.h>
#include <cstdint>
#include <cstddef>

#define D 128
#define HID 384
#define MAXN 100000
#define MAXE 500000
#define MAXG 5000

// ---------------------------------------------------------------------------
// Scratch layout (floats)
// ---------------------------------------------------------------------------
static const size_t OFF_ZB = 0;                                    // E*384
static const size_t OFF_PH = OFF_ZB + (size_t)MAXE * HID;          // N*384 halves (reuses fp32-sized slot)
static const size_t OFF_U1 = OFF_PH + (size_t)MAXN * HID;          // G*384
static const size_t OFF_ZA = OFF_U1 + (size_t)MAXG * HID;          // N*384
static const size_t OFF_ZG = OFF_ZA + (size_t)MAXN * HID;          // G*384
static const size_t OFF_SH = OFF_ZG + (size_t)MAXG * HID;          // N*128
static const size_t OFF_SE = OFF_SH + (size_t)MAXN * D;            // N*128
static const size_t OFF_UH = OFF_SE + (size_t)MAXN * D;            // G*128
static const size_t OFF_UE = OFF_UH + (size_t)MAXG * D;            // G*128
static const size_t OFF_ST = OFF_UE + (size_t)MAXG * D;            // 4*384
static const size_t OFF_WP   = OFF_ST + 4 * HID;                   // 589824 halves
static const size_t OFF_XA16 = OFF_WP + 294912;                    // N*384 halves
static const size_t OFF_XG16 = OFF_XA16 + (size_t)MAXN * HID / 2;  // G*384 halves
static const size_t OFF_E16  = OFF_XG16 + (size_t)MAXG * HID / 2;  // E*128 halves
static const size_t OFF_H16  = OFF_E16 + (size_t)MAXE * D / 2;     // N*128 halves
static const size_t OFF_U16  = OFF_H16 + (size_t)MAXN * D / 2;     // G*128 halves
static const size_t TOTAL_SCRATCH = OFF_U16 + (size_t)MAXG * D / 2 + 1024;

__device__ __align__(256) float g_scratch[TOTAL_SCRATCH];

// Prepped-weight offsets in half elements (dense fp16).
#define WPO_BW1A 0
#define WPO_BW1B 49152
#define WPO_BW1C 98304
#define WPO_BW2  147456
#define WPO_AW1  196608
#define WPO_AW2  344064
#define WPO_GW1  393216
#define WPO_GW2  540672

// ---------------------------------------------------------------------------
// PTX helpers (arch-agnostic: ldmatrix sm_75+, fp16 mma sm_80+, cp.async sm_80+)
// ---------------------------------------------------------------------------
__device__ __forceinline__ uint32_t smem_u32(const void* p) {
    uint32_t a;
    asm("{ .reg .u64 t; cvta.to.shared.u64 t, %1; cvt.u32.u64 %0, t; }" : "=r"(a) : "l"(p));
    return a;
}
__device__ __forceinline__ void ldsm4(uint32_t (&r)[4], uint32_t addr) {
    asm volatile("ldmatrix.sync.aligned.m8n8.x4.shared.b16 {%0,%1,%2,%3}, [%4];"
                 : "=r"(r[0]), "=r"(r[1]), "=r"(r[2]), "=r"(r[3]) : "r"(addr));
}
__device__ __forceinline__ void ldsm4t(uint32_t (&r)[4], uint32_t addr) {
    asm volatile("ldmatrix.sync.aligned.m8n8.x4.trans.shared.b16 {%0,%1,%2,%3}, [%4];"
                 : "=r"(r[0]), "=r"(r[1]), "=r"(r[2]), "=r"(r[3]) : "r"(addr));
}
__device__ __forceinline__ void mma16816(float (&c)[4], const uint32_t (&a)[4],
                                         uint32_t b0, uint32_t b1) {
    asm volatile(
        "mma.sync.aligned.m16n8k16.row.col.f32.f16.f16.f32 "
        "{%0,%1,%2,%3}, {%4,%5,%6,%7}, {%8,%9}, {%0,%1,%2,%3};"
        : "+f"(c[0]), "+f"(c[1]), "+f"(c[2]), "+f"(c[3])
        : "r"(a[0]), "r"(a[1]), "r"(a[2]), "r"(a[3]), "r"(b0), "r"(b1));
}
__device__ __forceinline__ uint32_t packh2(float x, float y) {
    __half2 p = __halves2half2(__float2half_rn(x), __float2half_rn(y));
    return *(uint32_t*)&p;
}
__device__ __forceinline__ void cp_async16(uint32_t saddr, const void* gaddr) {
    asm volatile("cp.async.cg.shared.global [%0], [%1], 16;" :: "r"(saddr), "l"(gaddr));
}
__device__ __forceinline__ void cp_async16z(uint32_t saddr, const void* gaddr, bool valid) {
    int sz = valid ? 16 : 0;
    asm volatile("cp.async.cg.shared.global [%0], [%1], 16, %2;"
                 :: "r"(saddr), "l"(gaddr), "r"(sz));
}
__device__ __forceinline__ void cp_commit() {
    asm volatile("cp.async.commit_group;" ::: "memory");
}
__device__ __forceinline__ void cp_wait0() {
    asm volatile("cp.async.wait_group 0;" ::: "memory");
}
__device__ __forceinline__ void cp_wait1() {
    asm volatile("cp.async.wait_group 1;" ::: "memory");
}

// ---------------------------------------------------------------------------
// prep kernels: fp32 -> fp16 (dense)
// ---------------------------------------------------------------------------
__global__ void prep_weight(const float* __restrict__ W, __half* __restrict__ out,
                            int total)
{
    int i = blockIdx.x * blockDim.x + threadIdx.x;
    if (i >= total) return;
    out[i] = __float2half_rn(W[i]);
}
__global__ void cvt_half4(const float* __restrict__ in, __half* __restrict__ out, int n4)
{
    int i = blockIdx.x * blockDim.x + threadIdx.x;
    if (i >= n4) return;
    float4 v = ((const float4*)in)[i];
    uint2 w;
    w.x = packh2(v.x, v.y);
    w.y = packh2(v.z, v.w);
    ((uint2*)out)[i] = w;
}

// ---------------------------------------------------------------------------
// mma.sync GEMM: C[M,Nd] = op(A)[M,K] @ W[K,Nd] (+bias), fp32 accumulate.
//  HALFA: A already fp16 in gmem -> staged via cp.async
//  BNA:   (fp32 A) relu(a*scale+shift) applied at staging
//  GATH:  epilogue adds Ph16[src[r]] + Ph16[dst[r]] (fp16, L2-resident) + U1[gid[src]]
//  SCAT:  epilogue atomicAdds rows into segout[seg[r]]
//  STATS: per-column sum/sumsq (from fp32 values, pre-any-storage-truncation)
//  HSCAT: (col0==0 CTAs) SH[dst[r]] += h[src[r]]
//  HALFC: C written as fp16 (used for Ph so it stays L2-resident)
// 128x128 tile, 256 threads, KC=32, 2 CTAs/SM, B (and A when HALFA) dbl-buffered.
// ---------------------------------------------------------------------------
#define APAD 80
#define BPAD 272

template<bool HALFA, bool BNA, bool SCAT, bool GATH, bool STATS, bool HSCAT, bool HALFC>
__global__ void __launch_bounds__(256, 2)
gemm_mma(const void* __restrict__ Avoid, const __half* __restrict__ Bp,
         const float* __restrict__ bias, void* __restrict__ Cvoid,
         int M, int K, int Nd,
         const float* __restrict__ bnscale, const float* __restrict__ bnshift,
         const int* __restrict__ seg, float* __restrict__ segout,
         const __half* __restrict__ Ph16, const float* __restrict__ U1,
         const int* __restrict__ src, const int* __restrict__ dst,
         const int* __restrict__ gid,
         float* __restrict__ st_sum, float* __restrict__ st_sq,
         const float* __restrict__ Hg, float* __restrict__ SHg)
{
    __shared__ __align__(16) char sA[2][128 * APAD];
    __shared__ __align__(16) char sB[2][32 * BPAD];
    __shared__ float ssc[HID];
    __shared__ float ssh[HID];
    __shared__ float ssum[128];
    __shared__ float ssq[128];

    const int tid  = threadIdx.x;
    const int wid  = tid >> 5;
    const int lane = tid & 31;
    const int wm   = wid & 3;
    const int wn   = wid >> 2;
    const int row0 = blockIdx.y * 128;
    const int col0 = blockIdx.x * 128;

    if (BNA) {
        for (int i = tid; i < K; i += 256) { ssc[i] = bnscale[i]; ssh[i] = bnshift[i]; }
    }
    if (STATS && tid < 128) { ssum[tid] = 0.f; ssq[tid] = 0.f; }

    const int arow = tid >> 1;
    const int acol = (tid & 1) * 16;
    const bool avalid = (row0 + arow) < M;
    const float*  Af = (const float*) Avoid + (size_t)(row0 + arow) * K + acol;
    const __half* Ah = (const __half*)Avoid + (size_t)(row0 + arow) * K + acol;

    const int brow = tid >> 3;
    const int bcol = (tid & 7) * 16;

    float acc[2][8][4];
    #pragma unroll
    for (int i = 0; i < 2; i++)
        #pragma unroll
        for (int j = 0; j < 8; j++)
            #pragma unroll
            for (int q = 0; q < 4; q++) acc[i][j][q] = 0.f;

    const uint32_t aB0 = smem_u32(sA[0]);
    const uint32_t aB1 = smem_u32(sA[1]);
    const uint32_t bB0 = smem_u32(sB[0]);
    const uint32_t bB1 = smem_u32(sB[1]);

    const uint32_t aoff = (uint32_t)((lane & 15) * APAD + (lane >> 4) * 16);
    const uint32_t boff = (uint32_t)((((lane >> 3) & 1) * 8 + (lane & 7)) * BPAD + (lane >> 4) * 16);

    const int nchunk = K >> 5;
    const uint32_t bdst = (uint32_t)(brow * BPAD + bcol * 2);
    const uint32_t adst = (uint32_t)(arow * APAD + acol * 2);

    float4 aval[4];

    if (HALFA) {
        cp_async16z(aB0 + adst,      Ah,     avalid);
        cp_async16z(aB0 + adst + 16, Ah + 8, avalid);
        cp_async16(bB0 + bdst,      Bp + (size_t)brow * Nd + col0 + bcol);
        cp_async16(bB0 + bdst + 16, Bp + (size_t)brow * Nd + col0 + bcol + 8);
        cp_commit();
    } else {
        cp_async16(bB0 + bdst,      Bp + (size_t)brow * Nd + col0 + bcol);
        cp_async16(bB0 + bdst + 16, Bp + (size_t)brow * Nd + col0 + bcol + 8);
        cp_commit();
        if (avalid) {
            #pragma unroll
            for (int q = 0; q < 4; q++) aval[q] = *(const float4*)(Af + q * 4);
        } else {
            #pragma unroll
            for (int q = 0; q < 4; q++) aval[q] = make_float4(0.f, 0.f, 0.f, 0.f);
        }
    }
    __syncthreads();

    for (int c = 0; c < nchunk; c++) {
        const int buf = c & 1;
        if (HALFA) {
            if (c + 1 < nchunk) {
                const uint32_t na = (buf ^ 1) ? aB1 : aB0;
                const uint32_t nb = (buf ^ 1) ? bB1 : bB0;
                cp_async16z(na + adst,      Ah + (c + 1) * 32,     avalid);
                cp_async16z(na + adst + 16, Ah + (c + 1) * 32 + 8, avalid);
                const __half* bp = Bp + (size_t)((c + 1) * 32 + brow) * Nd + col0 + bcol;
                cp_async16(nb + bdst, bp);
                cp_async16(nb + bdst + 16, bp + 8);
                cp_commit();
                cp_wait1();
            } else {
                cp_wait0();
            }
            __syncthreads();
        } else {
            if (c > 0) __syncthreads();
            {
                const int kb = c * 32 + acol;
                char* ah = sA[0] + adst;
                #pragma unroll
                for (int q = 0; q < 4; q++) {
                    float4 v = aval[q];
                    if (BNA) {
                        const int k = kb + q * 4;
                        v.x = fmaxf(fmaf(v.x, ssc[k + 0], ssh[k + 0]), 0.f);
                        v.y = fmaxf(fmaf(v.y, ssc[k + 1], ssh[k + 1]), 0.f);
                        v.z = fmaxf(fmaf(v.z, ssc[k + 2], ssh[k + 2]), 0.f);
                        v.w = fmaxf(fmaf(v.w, ssc[k + 3], ssh[k + 3]), 0.f);
                    }
                    uint2 hv;
                    hv.x = packh2(v.x, v.y);
                    hv.y = packh2(v.z, v.w);
                    *(uint2*)(ah + q * 8) = hv;
                }
            }
            if (c + 1 < nchunk) {
                const uint32_t nb = (buf ^ 1) ? bB1 : bB0;
                const __half* bp = Bp + (size_t)((c + 1) * 32 + brow) * Nd + col0 + bcol;
                cp_async16(nb + bdst, bp);
                cp_async16(nb + bdst + 16, bp + 8);
                cp_commit();
                cp_wait1();
            } else {
                cp_wait0();
            }
            __syncthreads();
            if (c + 1 < nchunk && avalid) {
                const float* ap = Af + (c + 1) * 32;
                #pragma unroll
                for (int q = 0; q < 4; q++) aval[q] = *(const float4*)(ap + q * 4);
            }
        }
        const uint32_t aBc = HALFA ? (buf ? aB1 : aB0) : aB0;
        const uint32_t bBc = buf ? bB1 : bB0;
        #pragma unroll
        for (int kk = 0; kk < 2; kk++) {
            uint32_t af[2][4], bx[8][2];
            #pragma unroll
            for (int p = 0; p < 4; p++) {
                uint32_t r[4];
                ldsm4t(r, bBc + boff + (uint32_t)(kk * 16 * BPAD + (64 * wn + p * 16) * 2));
                bx[2 * p][0] = r[0]; bx[2 * p][1] = r[1];
                bx[2 * p + 1][0] = r[2]; bx[2 * p + 1][1] = r[3];
            }
            #pragma unroll
            for (int i = 0; i < 2; i++)
                ldsm4(af[i], aBc + aoff + (uint32_t)((32 * wm + 16 * i) * APAD + kk * 32));
            #pragma unroll
            for (int i = 0; i < 2; i++)
                #pragma unroll
                for (int j = 0; j < 8; j++)
                    mma16816(acc[i][j], af[i], bx[j][0], bx[j][1]);
        }
        if (c + 1 < nchunk) __syncthreads();
    }

    // ---- epilogue ----
    const int m4 = lane >> 2;
    const int n2 = (lane & 3) * 2;
    const bool do_hscat = HSCAT && (col0 == 0);

    float bcolv[16];
    #pragma unroll
    for (int j = 0; j < 8; j++) {
        if (bias) {
            float2 b2 = *(const float2*)(bias + col0 + 64 * wn + 8 * j + n2);
            bcolv[2 * j] = b2.x; bcolv[2 * j + 1] = b2.y;
        } else {
            bcolv[2 * j] = 0.f; bcolv[2 * j + 1] = 0.f;
        }
    }
    float csum[16], csq[16];
    if (STATS) {
        #pragma unroll
        for (int q = 0; q < 16; q++) { csum[q] = 0.f; csq[q] = 0.f; }
    }

    #pragma unroll
    for (int i = 0; i < 2; i++) {
        const int rb = row0 + 32 * wm + 16 * i + m4;
        #pragma unroll
        for (int hf = 0; hf < 2; hf++) {
            const int r = rb + 8 * hf;
            if (r >= M) continue;
            int si = 0, di = 0, gi2 = 0, sg = 0;
            if (GATH) { si = src[r]; di = dst[r]; gi2 = gid[si]; }
            if (SCAT) sg = seg[r];
            #pragma unroll
            for (int j = 0; j < 8; j++) {
                const int gc = col0 + 64 * wn + 8 * j + n2;
                float v0 = acc[i][j][2 * hf]     + bcolv[2 * j];
                float v1 = acc[i][j][2 * hf + 1] + bcolv[2 * j + 1];
                if (GATH) {
                    __half2 p1 = *(const __half2*)(Ph16 + (size_t)si * HID + gc);
                    __half2 p2 = *(const __half2*)(Ph16 + (size_t)di * HID + gc);
                    float2 f1 = __half22float2(p1);
                    float2 f2 = __half22float2(p2);
                    float2 g3 = *(const float2*)(U1 + (size_t)gi2 * HID + gc);
                    v0 += f1.x + f2.x + g3.x;
                    v1 += f1.y + f2.y + g3.y;
                }
                if (HALFC) {
                    *(uint32_t*)((__half*)Cvoid + (size_t)r * Nd + gc) = packh2(v0, v1);
                } else {
                    *(float2*)((float*)Cvoid + (size_t)r * Nd + gc) = make_float2(v0, v1);
                }
                if (SCAT) {
                    float* so = segout + (size_t)sg * Nd + gc;
                    atomicAdd(so, v0); atomicAdd(so + 1, v1);
                }
                if (do_hscat) {
                    float2 hv2 = *(const float2*)(Hg + (size_t)si * D + gc);
                    float* so2 = SHg + (size_t)di * D + gc;
                    atomicAdd(so2, hv2.x); atomicAdd(so2 + 1, hv2.y);
                }
                if (STATS) {
                    csum[2 * j] += v0;     csq[2 * j] += v0 * v0;
                    csum[2 * j + 1] += v1; csq[2 * j + 1] += v1 * v1;
                }
            }
        }
    }
    if (STATS) {
        #pragma unroll
        for (int j = 0; j < 8; j++) {
            const int cl0 = 64 * wn + 8 * j + n2;
            atomicAdd(&ssum[cl0], csum[2 * j]);
            atomicAdd(&ssum[cl0 + 1], csum[2 * j + 1]);
            atomicAdd(&ssq[cl0], csq[2 * j]);
            atomicAdd(&ssq[cl0 + 1], csq[2 * j + 1]);
        }
        __syncthreads();
        if (tid < 128) {
            atomicAdd(&st_sum[col0 + tid], ssum[tid]);
            atomicAdd(&st_sq[col0 + tid], ssq[tid]);
        }
    }
}

// ---------------------------------------------------------------------------
// Elementwise kernels
// ---------------------------------------------------------------------------
__global__ void zerok(float* __restrict__ p, size_t n) {
    size_t i = (size_t)blockIdx.x * blockDim.x + threadIdx.x;
    size_t st = (size_t)gridDim.x * blockDim.x;
    for (; i < n; i += st) p[i] = 0.f;
}

__global__ void bn_prep(float* __restrict__ sum, float* __restrict__ sq,
                        const float* __restrict__ g1, const float* __restrict__ beta1,
                        float* __restrict__ scale, float* __restrict__ shift, float invM)
{
    const int c = threadIdx.x;
    float mean = sum[c] * invM;
    float var  = sq[c] * invM - mean * mean;
    float rstd = rsqrtf(var + 1e-5f);
    float sc = rstd * g1[c];
    scale[c] = sc;
    shift[c] = beta1[c] - mean * sc;
    sum[c] = 0.f;
    sq[c] = 0.f;
}

__global__ void node_build(const float* __restrict__ h, const float* __restrict__ u,
                           const int* __restrict__ gid,
                           const float* __restrict__ SH, const float* __restrict__ SE,
                           __half* __restrict__ Xa16, float* __restrict__ UE, int N)
{
    int idx = blockIdx.x * blockDim.x + threadIdx.x;
    int tot = N * 32;
    if (idx >= tot) return;
    int n = idx >> 5;
    int c = (idx & 31) << 2;
    int g = gid[n];
    float4 sh = *(const float4*)&SH[(size_t)n * D + c];
    float4 hv = *(const float4*)&h[(size_t)n * D + c];
    float4 se = *(const float4*)&SE[(size_t)n * D + c];
    float4 uv = *(const float4*)&u[(size_t)g * D + c];
    size_t base = (size_t)n * HID;
    uint2 w;
    w.x = packh2(sh.x + hv.x, sh.y + hv.y);
    w.y = packh2(sh.z + hv.z, sh.w + hv.w);
    *(uint2*)&Xa16[base + c] = w;
    w.x = packh2(se.x, se.y);
    w.y = packh2(se.z, se.w);
    *(uint2*)&Xa16[base + D + c] = w;
    w.x = packh2(uv.x, uv.y);
    w.y = packh2(uv.z, uv.w);
    *(uint2*)&Xa16[base + 2 * D + c] = w;
    float* o = UE + (size_t)g * D + c;
    atomicAdd(o + 0, 0.5f * se.x); atomicAdd(o + 1, 0.5f * se.y);
    atomicAdd(o + 2, 0.5f * se.z); atomicAdd(o + 3, 0.5f * se.w);
}

__global__ void graph_build(const float* __restrict__ u, const float* __restrict__ UH,
                            const float* __restrict__ UE, __half* __restrict__ Xg16, int G)
{
    int idx = blockIdx.x * blockDim.x + threadIdx.x;
    int tot = G * 32;
    if (idx >= tot) return;
    int g = idx >> 5;
    int c = (idx & 31) << 2;
    size_t base = (size_t)g * HID;
    float4 a = *(const float4*)&UH[(size_t)g * D + c];
    float4 b = *(const float4*)&UE[(size_t)g * D + c];
    float4 d = *(const float4*)&u[(size_t)g * D + c];
    uint2 w;
    w.x = packh2(a.x, a.y); w.y = packh2(a.z, a.w);
    *(uint2*)&Xg16[base + c] = w;
    w.x = packh2(b.x, b.y); w.y = packh2(b.z, b.w);
    *(uint2*)&Xg16[base + D + c] = w;
    w.x = packh2(d.x, d.y); w.y = packh2(d.z, d.w);
    *(uint2*)&Xg16[base + 2 * D + c] = w;
}

// ---------------------------------------------------------------------------
// Dispatch.
// mode 0: HALFA plain            mode 5: HALFA + HALFC (Ph output fp16)
// mode 1: HALFA GATH+STATS+HSCAT mode 2: fp32 BNA+SCAT
// mode 3: HALFA STATS            mode 4: fp32 BNA
// ---------------------------------------------------------------------------
static void run_gemm_mma(int mode,
                         const void* A, const __half* Bp, const float* bias, void* C,
                         int M, int K, int Nd,
                         const float* sc, const float* sh,
                         const int* seg, float* segout,
                         const __half* Ph16, const float* U1,
                         const int* src, const int* dst, const int* gid,
                         float* st_sum, float* st_sq,
                         const float* Hg, float* SHg)
{
    dim3 grid(Nd / 128, (M + 127) / 128);
    switch (mode) {
    case 0: gemm_mma<true ,false,false,false,false,false,false><<<grid,256>>>(A,Bp,bias,C,M,K,Nd,sc,sh,seg,segout,Ph16,U1,src,dst,gid,st_sum,st_sq,Hg,SHg); break;
    case 5: gemm_mma<true ,false,false,false,false,false,true ><<<grid,256>>>(A,Bp,bias,C,M,K,Nd,sc,sh,seg,segout,Ph16,U1,src,dst,gid,st_sum,st_sq,Hg,SHg); break;
    case 1: gemm_mma<true ,false,false,true ,true ,true ,false><<<grid,256>>>(A,Bp,bias,C,M,K,Nd,sc,sh,seg,segout,Ph16,U1,src,dst,gid,st_sum,st_sq,Hg,SHg); break;
    case 2: gemm_mma<false,true ,true ,false,false,false,false><<<grid,256>>>(A,Bp,bias,C,M,K,Nd,sc,sh,seg,segout,Ph16,U1,src,dst,gid,st_sum,st_sq,Hg,SHg); break;
    case 3: gemm_mma<true ,false,false,false,true ,false,false><<<grid,256>>>(A,Bp,bias,C,M,K,Nd,sc,sh,seg,segout,Ph16,U1,src,dst,gid,st_sum,st_sq,Hg,SHg); break;
    case 4: gemm_mma<false,true ,false,false,false,false,false><<<grid,256>>>(A,Bp,bias,C,M,K,Nd,sc,sh,seg,segout,Ph16,U1,src,dst,gid,st_sum,st_sq,Hg,SHg); break;
    }
}

extern "C" void kernel_launch(void* const* d_in, const int* in_sizes, int n_in,
                              void* d_out, int out_size)
{
    const float* h   = (const float*)d_in[0];
    const float* e   = (const float*)d_in[1];
    const float* u   = (const float*)d_in[2];
    const int*   src = (const int*)d_in[3];
    const int*   dst = (const int*)d_in[4];
    const int*   gid = (const int*)d_in[5];

    const float* bW1 = (const float*)d_in[6];
    const float* bb1 = (const float*)d_in[7];
    const float* bg1 = (const float*)d_in[8];
    const float* bbt = (const float*)d_in[9];
    const float* bW2 = (const float*)d_in[10];
    const float* bb2 = (const float*)d_in[11];

    const float* aW1 = (const float*)d_in[12];
    const float* ab1 = (const float*)d_in[13];
    const float* ag1 = (const float*)d_in[14];
    const float* abt = (const float*)d_in[15];
    const float* aW2 = (const float*)d_in[16];
    const float* ab2 = (const float*)d_in[17];

    const float* gW1 = (const float*)d_in[18];
    const float* gb1 = (const float*)d_in[19];
    const float* gg1 = (const float*)d_in[20];
    const float* gbt = (const float*)d_in[21];
    const float* gW2 = (const float*)d_in[22];
    const float* gb2 = (const float*)d_in[23];

    const int N = in_sizes[5];
    const int E = in_sizes[3];
    const int G = in_sizes[2] / D;

    float* scratch = nullptr;
    cudaGetSymbolAddress((void**)&scratch, g_scratch);

    float* Zb = scratch + OFF_ZB;
    __half* Ph16 = (__half*)(scratch + OFF_PH);
    float* U1 = scratch + OFF_U1;
    float* Za = scratch + OFF_ZA;
    float* Zg = scratch + OFF_ZG;
    float* SH = scratch + OFF_SH;
    float* SE = scratch + OFF_SE;
    float* UH = scratch + OFF_UH;
    float* UE = scratch + OFF_UE;
    float* st_sum   = scratch + OFF_ST;
    float* st_sq    = st_sum + HID;
    float* bn_scale = st_sq + HID;
    float* bn_shift = bn_scale + HID;
    __half* WP   = (__half*)(scratch + OFF_WP);
    __half* Xa16 = (__half*)(scratch + OFF_XA16);
    __half* Xg16 = (__half*)(scratch + OFF_XG16);
    __half* e16  = (__half*)(scratch + OFF_E16);
    __half* h16  = (__half*)(scratch + OFF_H16);
    __half* u16  = (__half*)(scratch + OFF_U16);

    float* out_h = (float*)d_out;
    float* out_e = out_h + (size_t)N * D;
    float* out_u = out_e + (size_t)E * D;

    // Zero accumulators (SH, SE, UH, UE, stats) — contiguous region.
    {
        size_t nz = (size_t)MAXN * D * 2 + (size_t)MAXG * D * 2 + 2 * HID;
        zerok<<<2048, 256>>>(SH, nz);
    }

    // Pre-convert inputs + weights to fp16.
    {
        cvt_half4<<<(E * D / 4 + 255) / 256, 256>>>(e, e16, E * D / 4);
        cvt_half4<<<(N * D / 4 + 255) / 256, 256>>>(h, h16, N * D / 4);
        cvt_half4<<<(G * D / 4 + 255) / 256, 256>>>(u, u16, G * D / 4);
        const int T1 = 128 * HID, T2 = HID * HID, T3 = HID * D;
        prep_weight<<<(T1 + 255) / 256, 256>>>(bW1,                       WP + WPO_BW1A, T1);
        prep_weight<<<(T1 + 255) / 256, 256>>>(bW1 + (size_t)D * HID,     WP + WPO_BW1B, T1);
        prep_weight<<<(T1 + 255) / 256, 256>>>(bW1 + (size_t)2 * D * HID, WP + WPO_BW1C, T1);
        prep_weight<<<(T3 + 255) / 256, 256>>>(bW2, WP + WPO_BW2, T3);
        prep_weight<<<(T2 + 255) / 256, 256>>>(aW1, WP + WPO_AW1, T2);
        prep_weight<<<(T3 + 255) / 256, 256>>>(aW2, WP + WPO_AW2, T3);
        prep_weight<<<(T2 + 255) / 256, 256>>>(gW1, WP + WPO_GW1, T2);
        prep_weight<<<(T3 + 255) / 256, 256>>>(gW2, WP + WPO_GW2, T3);
    }

    // ---- Bond path ----
    // Ph16 = fp16( h16 @ bW1a )  — stays L2-resident (77 MB)
    run_gemm_mma(5, h16, WP + WPO_BW1A, nullptr, Ph16, N, 128, HID,
                 nullptr, nullptr, nullptr, nullptr, nullptr, nullptr, nullptr, nullptr, nullptr,
                 nullptr, nullptr, nullptr, nullptr);
    run_gemm_mma(0, u16, WP + WPO_BW1C, bb1, U1, G, 128, HID,
                 nullptr, nullptr, nullptr, nullptr, nullptr, nullptr, nullptr, nullptr, nullptr,
                 nullptr, nullptr, nullptr, nullptr);
    // Zb = e@bW1b + Ph16[src] + Ph16[dst] + U1[gid[src]]; fused stats + SH scatter
    run_gemm_mma(1, e16, WP + WPO_BW1B, nullptr, Zb, E, 128, HID,
                 nullptr, nullptr, nullptr, nullptr, Ph16, U1, src, dst, gid, st_sum, st_sq,
                 h, SH);
    bn_prep<<<1, HID>>>(st_sum, st_sq, bg1, bbt, bn_scale, bn_shift, 1.f / (float)E);
    // e_new = relu(BN(Zb)) @ bW2 + bb2 ; SE[dst] += e_new
    run_gemm_mma(2, Zb, WP + WPO_BW2, bb2, out_e, E, HID, D,
                 bn_scale, bn_shift, dst, SE, nullptr, nullptr, nullptr, nullptr, nullptr,
                 nullptr, nullptr, nullptr, nullptr);

    // ---- Atom path ----
    node_build<<<(N * 32 + 255) / 256, 256>>>(h, u, gid, SH, SE, Xa16, UE, N);
    run_gemm_mma(3, Xa16, WP + WPO_AW1, ab1, Za, N, HID, HID,
                 nullptr, nullptr, nullptr, nullptr, nullptr, nullptr, nullptr, nullptr, nullptr,
                 st_sum, st_sq, nullptr, nullptr);
    bn_prep<<<1, HID>>>(st_sum, st_sq, ag1, abt, bn_scale, bn_shift, 1.f / (float)N);
    run_gemm_mma(2, Za, WP + WPO_AW2, ab2, out_h, N, HID, D,
                 bn_scale, bn_shift, gid, UH, nullptr, nullptr, nullptr, nullptr, nullptr,
                 nullptr, nullptr, nullptr, nullptr);

    // ---- Global path ----
    graph_build<<<(G * 32 + 255) / 256, 256>>>(u, UH, UE, Xg16, G);
    run_gemm_mma(3, Xg16, WP + WPO_GW1, gb1, Zg, G, HID, HID,
                 nullptr, nullptr, nullptr, nullptr, nullptr, nullptr, nullptr, nullptr, nullptr,
                 st_sum, st_sq, nullptr, nullptr);
    bn_prep<<<1, HID>>>(st_sum, st_sq, gg1, gbt, bn_scale, bn_shift, 1.f / (float)G);
    run_gemm_mma(4, Zg, WP + WPO_GW2, gb2, out_u, G, HID, D,
                 bn_scale, bn_shift, nullptr, nullptr, nullptr, nullptr, nullptr, nullptr, nullptr,
                 nullptr, nullptr, nullptr, nullptr);
}

// round 15
// speedup vs baseline: 1.1745x; 1.0066x over previous
#include <cuda_runtime.h>
#include <cuda_fp16.h>
#include <cstdint>
#include <cstddef>

#define D 128
#define HID 384
#define MAXN 100000
#define MAXE 500000
#define MAXG 5000

// ---------------------------------------------------------------------------
// Scratch layout (floats)
// ---------------------------------------------------------------------------
static const size_t OFF_ZB = 0;                                    // E*384 fp32
static const size_t OFF_PH = OFF_ZB + (size_t)MAXE * HID;          // N*384 halves
static const size_t OFF_U1 = OFF_PH + (size_t)MAXN * HID;          // G*384 fp32
static const size_t OFF_ZA = OFF_U1 + (size_t)MAXG * HID;          // N*384 fp32
static const size_t OFF_ZG = OFF_ZA + (size_t)MAXN * HID;          // G*384 fp32
static const size_t OFF_SH = OFF_ZG + (size_t)MAXG * HID;          // N*128
static const size_t OFF_SE = OFF_SH + (size_t)MAXN * D;            // N*128
static const size_t OFF_UH = OFF_SE + (size_t)MAXN * D;            // G*128
static const size_t OFF_UE = OFF_UH + (size_t)MAXG * D;            // G*128
static const size_t OFF_ST = OFF_UE + (size_t)MAXG * D;            // 4*384
static const size_t OFF_WP   = OFF_ST + 4 * HID;                   // 589824 halves
static const size_t OFF_XA16 = OFF_WP + 294912;                    // N*384 halves
static const size_t OFF_XG16 = OFF_XA16 + (size_t)MAXN * HID / 2;  // G*384 halves
static const size_t OFF_E16  = OFF_XG16 + (size_t)MAXG * HID / 2;  // E*128 halves
static const size_t OFF_H16  = OFF_E16 + (size_t)MAXE * D / 2;     // N*128 halves
static const size_t OFF_U16  = OFF_H16 + (size_t)MAXN * D / 2;     // G*128 halves
static const size_t TOTAL_SCRATCH = OFF_U16 + (size_t)MAXG * D / 2 + 1024;

__device__ __align__(256) float g_scratch[TOTAL_SCRATCH];

// Prepped-weight offsets in half elements (dense fp16).
#define WPO_BW1A 0
#define WPO_BW1B 49152
#define WPO_BW1C 98304
#define WPO_BW2  147456
#define WPO_AW1  196608
#define WPO_AW2  344064
#define WPO_GW1  393216
#define WPO_GW2  540672

// ---------------------------------------------------------------------------
// PTX helpers
// ---------------------------------------------------------------------------
__device__ __forceinline__ uint32_t smem_u32(const void* p) {
    uint32_t a;
    asm("{ .reg .u64 t; cvta.to.shared.u64 t, %1; cvt.u32.u64 %0, t; }" : "=r"(a) : "l"(p));
    return a;
}
__device__ __forceinline__ void ldsm4(uint32_t (&r)[4], uint32_t addr) {
    asm volatile("ldmatrix.sync.aligned.m8n8.x4.shared.b16 {%0,%1,%2,%3}, [%4];"
                 : "=r"(r[0]), "=r"(r[1]), "=r"(r[2]), "=r"(r[3]) : "r"(addr));
}
__device__ __forceinline__ void ldsm4t(uint32_t (&r)[4], uint32_t addr) {
    asm volatile("ldmatrix.sync.aligned.m8n8.x4.trans.shared.b16 {%0,%1,%2,%3}, [%4];"
                 : "=r"(r[0]), "=r"(r[1]), "=r"(r[2]), "=r"(r[3]) : "r"(addr));
}
__device__ __forceinline__ void mma16816(float (&c)[4], const uint32_t (&a)[4],
                                         uint32_t b0, uint32_t b1) {
    asm volatile(
        "mma.sync.aligned.m16n8k16.row.col.f32.f16.f16.f32 "
        "{%0,%1,%2,%3}, {%4,%5,%6,%7}, {%8,%9}, {%0,%1,%2,%3};"
        : "+f"(c[0]), "+f"(c[1]), "+f"(c[2]), "+f"(c[3])
        : "r"(a[0]), "r"(a[1]), "r"(a[2]), "r"(a[3]), "r"(b0), "r"(b1));
}
__device__ __forceinline__ uint32_t packh2(float x, float y) {
    __half2 p = __halves2half2(__float2half_rn(x), __float2half_rn(y));
    return *(uint32_t*)&p;
}
__device__ __forceinline__ void cp_async16(uint32_t saddr, const void* gaddr) {
    asm volatile("cp.async.cg.shared.global [%0], [%1], 16;" :: "r"(saddr), "l"(gaddr));
}
__device__ __forceinline__ void cp_async16z(uint32_t saddr, const void* gaddr, bool valid) {
    int sz = valid ? 16 : 0;
    asm volatile("cp.async.cg.shared.global [%0], [%1], 16, %2;"
                 :: "r"(saddr), "l"(gaddr), "r"(sz));
}
__device__ __forceinline__ void cp_commit() {
    asm volatile("cp.async.commit_group;" ::: "memory");
}
__device__ __forceinline__ void cp_wait2() {
    asm volatile("cp.async.wait_group 2;" ::: "memory");
}

// ---------------------------------------------------------------------------
// Fused prep kernels
// ---------------------------------------------------------------------------
__global__ void cvt_all(const float* __restrict__ e, const float* __restrict__ h,
                        const float* __restrict__ u,
                        __half* __restrict__ e16, __half* __restrict__ h16,
                        __half* __restrict__ u16, int ne4, int nh4, int nu4)
{
    int i = blockIdx.x * blockDim.x + threadIdx.x;
    const float* src; __half* dst; int j;
    if (i < ne4) { src = e; dst = e16; j = i; }
    else if (i < ne4 + nh4) { src = h; dst = h16; j = i - ne4; }
    else if (i < ne4 + nh4 + nu4) { src = u; dst = u16; j = i - ne4 - nh4; }
    else return;
    float4 v = ((const float4*)src)[j];
    uint2 w;
    w.x = packh2(v.x, v.y);
    w.y = packh2(v.z, v.w);
    ((uint2*)dst)[j] = w;
}

#define T1 49152
#define T2 147456
#define T3 49152
__global__ void prep_all(const float* __restrict__ bW1, const float* __restrict__ bW2,
                         const float* __restrict__ aW1, const float* __restrict__ aW2,
                         const float* __restrict__ gW1, const float* __restrict__ gW2,
                         __half* __restrict__ WP)
{
    int i = blockIdx.x * blockDim.x + threadIdx.x;
    const float* src; int dstoff;
    if      (i < T1)                  { src = bW1;               dstoff = WPO_BW1A; }
    else if (i < 2*T1)                { src = bW1 + T1;          dstoff = WPO_BW1B; i -= T1; }
    else if (i < 3*T1)                { src = bW1 + 2*T1;        dstoff = WPO_BW1C; i -= 2*T1; }
    else if (i < 3*T1 + T3)           { src = bW2;               dstoff = WPO_BW2;  i -= 3*T1; }
    else if (i < 3*T1 + T3 + T2)      { src = aW1;               dstoff = WPO_AW1;  i -= 3*T1 + T3; }
    else if (i < 3*T1 + 2*T3 + T2)    { src = aW2;               dstoff = WPO_AW2;  i -= 3*T1 + T3 + T2; }
    else if (i < 3*T1 + 2*T3 + 2*T2)  { src = gW1;               dstoff = WPO_GW1;  i -= 3*T1 + 2*T3 + T2; }
    else if (i < 3*T1 + 3*T3 + 2*T2)  { src = gW2;               dstoff = WPO_GW2;  i -= 3*T1 + 2*T3 + 2*T2; }
    else return;
    WP[dstoff + i] = __float2half_rn(src[i]);
}

// ---------------------------------------------------------------------------
// mma.sync GEMM with 4-stage cp.async pipeline (loads issued 3 chunks ahead).
//  HALFA: A fp16 in gmem, staged via cp.async (4-stage ring)
//  BNA:   (fp32 A) relu(a*scale+shift) at staging (A: reg prefetch + 2-stage)
//  GATH / SCAT / STATS / HSCAT / HALFC: as before
// 128x128 tile, 256 threads, KC=32, 2 CTAs/SM, dynamic smem 78KB.
// R15 FIX vs R14: pre-loop __syncthreads() restored — the BNA store stage of
// iteration 0 reads ssc/ssh, which other threads initialize; R14's first
// barrier came after that read (init race -> rel_err 1.9e-2).
// ---------------------------------------------------------------------------
#define APAD 80
#define BPAD 272
#define ASTAGE 10240
#define BSTAGE 8704
#define SM_B    40960
#define SM_SSC  75776
#define SM_SSH  77312
#define SM_SSUM 78848
#define SM_SSQ  79360
#define SMEM_BYTES 79872

template<bool HALFA, bool BNA, bool SCAT, bool GATH, bool STATS, bool HSCAT, bool HALFC>
__global__ void __launch_bounds__(256, 2)
gemm_mma(const void* __restrict__ Avoid, const __half* __restrict__ Bp,
         const float* __restrict__ bias, void* __restrict__ Cvoid,
         int M, int K, int Nd,
         const float* __restrict__ bnscale, const float* __restrict__ bnshift,
         const int* __restrict__ seg, float* __restrict__ segout,
         const __half* __restrict__ Ph16, const float* __restrict__ U1,
         const int* __restrict__ src, const int* __restrict__ dst,
         const int* __restrict__ gid,
         float* __restrict__ st_sum, float* __restrict__ st_sq,
         const float* __restrict__ Hg, float* __restrict__ SHg)
{
    extern __shared__ __align__(16) char smem[];
    float* ssc  = (float*)(smem + SM_SSC);
    float* ssh  = (float*)(smem + SM_SSH);
    float* ssum = (float*)(smem + SM_SSUM);
    float* ssq  = (float*)(smem + SM_SSQ);

    const int tid  = threadIdx.x;
    const int wid  = tid >> 5;
    const int lane = tid & 31;
    const int wm   = wid & 3;
    const int wn   = wid >> 2;
    const int row0 = blockIdx.y * 128;
    const int col0 = blockIdx.x * 128;

    if (BNA) {
        for (int i = tid; i < K; i += 256) { ssc[i] = bnscale[i]; ssh[i] = bnshift[i]; }
    }
    if (STATS && tid < 128) { ssum[tid] = 0.f; ssq[tid] = 0.f; }

    const int arow = tid >> 1;
    const int acol = (tid & 1) * 16;
    const bool avalid = (row0 + arow) < M;
    const float*  Af = (const float*) Avoid + (size_t)(row0 + arow) * K + acol;
    const __half* Ah = (const __half*)Avoid + (size_t)(row0 + arow) * K + acol;

    const int brow = tid >> 3;
    const int bcol = (tid & 7) * 16;

    float acc[2][8][4];
    #pragma unroll
    for (int i = 0; i < 2; i++)
        #pragma unroll
        for (int j = 0; j < 8; j++)
            #pragma unroll
            for (int q = 0; q < 4; q++) acc[i][j][q] = 0.f;

    const uint32_t sbase = smem_u32(smem);
    const uint32_t aoff = (uint32_t)((lane & 15) * APAD + (lane >> 4) * 16);
    const uint32_t boff = (uint32_t)((((lane >> 3) & 1) * 8 + (lane & 7)) * BPAD + (lane >> 4) * 16);

    const int nchunk = K >> 5;           // >= 4 always (K in {128, 384})
    const uint32_t bdst = (uint32_t)(brow * BPAD + bcol * 2);
    const uint32_t adst = (uint32_t)(arow * APAD + acol * 2);

    float4 aval[4];   // fp32-path register prefetch

    // ---- prologue: issue stages 0,1,2 (3 commit groups) ----
    #pragma unroll
    for (int s = 0; s < 3; s++) {
        const uint32_t bs = sbase + SM_B + (uint32_t)(s * BSTAGE);
        const __half* bp = Bp + (size_t)(s * 32 + brow) * Nd + col0 + bcol;
        cp_async16(bs + bdst, bp);
        cp_async16(bs + bdst + 16, bp + 8);
        if (HALFA) {
            const uint32_t as = sbase + (uint32_t)(s * ASTAGE);
            cp_async16z(as + adst,      Ah + s * 32,     avalid);
            cp_async16z(as + adst + 16, Ah + s * 32 + 8, avalid);
        }
        cp_commit();
    }
    if (!HALFA) {
        if (avalid) {
            #pragma unroll
            for (int q = 0; q < 4; q++) aval[q] = *(const float4*)(Af + q * 4);
        } else {
            #pragma unroll
            for (int q = 0; q < 4; q++) aval[q] = make_float4(0.f, 0.f, 0.f, 0.f);
        }
    }
    __syncthreads();   // R15 FIX: publish ssc/ssh/ssum BEFORE iter-0 BNA store reads them

    for (int c = 0; c < nchunk; c++) {
        // fp32 path: convert+store A chunk c into its 2-stage buffer.
        // (Last read of this buffer was compute(c-2), ordered by sync at c-1.)
        if (!HALFA) {
            const int kb = c * 32 + acol;
            char* ah = smem + (c & 1) * ASTAGE + adst;
            #pragma unroll
            for (int q = 0; q < 4; q++) {
                float4 v = aval[q];
                if (BNA) {
                    const int k = kb + q * 4;
                    v.x = fmaxf(fmaf(v.x, ssc[k + 0], ssh[k + 0]), 0.f);
                    v.y = fmaxf(fmaf(v.y, ssc[k + 1], ssh[k + 1]), 0.f);
                    v.z = fmaxf(fmaf(v.z, ssc[k + 2], ssh[k + 2]), 0.f);
                    v.w = fmaxf(fmaf(v.w, ssc[k + 3], ssh[k + 3]), 0.f);
                }
                uint2 hv;
                hv.x = packh2(v.x, v.y);
                hv.y = packh2(v.z, v.w);
                *(uint2*)(ah + q * 8) = hv;
            }
        }
        // Stage c landed: 3 groups were ahead of it; allow 2 outstanding.
        cp_wait2();
        __syncthreads();   // publishes stage c (+ fp32-A stores)
        // Issue stage c+3 into ring slot (c+3)&3 == (c-1)&3. Reads of that slot
        // finished in compute(c-1), ordered before this point by this sync.
        {
            const int s = c + 3;
            if (s < nchunk) {
                const uint32_t bs = sbase + SM_B + (uint32_t)((s & 3) * BSTAGE);
                const __half* bp = Bp + (size_t)(s * 32 + brow) * Nd + col0 + bcol;
                cp_async16(bs + bdst, bp);
                cp_async16(bs + bdst + 16, bp + 8);
                if (HALFA) {
                    const uint32_t as = sbase + (uint32_t)((s & 3) * ASTAGE);
                    cp_async16z(as + adst,      Ah + s * 32,     avalid);
                    cp_async16z(as + adst + 16, Ah + s * 32 + 8, avalid);
                }
            }
            cp_commit();   // constant one-group-per-iter rhythm
        }
        if (!HALFA && c + 1 < nchunk && avalid) {
            const float* ap = Af + (c + 1) * 32;
            #pragma unroll
            for (int q = 0; q < 4; q++) aval[q] = *(const float4*)(ap + q * 4);
        }
        // ---- compute chunk c ----
        const uint32_t aBc = sbase + (uint32_t)((HALFA ? (c & 3) : (c & 1)) * ASTAGE);
        const uint32_t bBc = sbase + SM_B + (uint32_t)((c & 3) * BSTAGE);
        #pragma unroll
        for (int kk = 0; kk < 2; kk++) {
            uint32_t af[2][4], bx[8][2];
            #pragma unroll
            for (int p = 0; p < 4; p++) {
                uint32_t r[4];
                ldsm4t(r, bBc + boff + (uint32_t)(kk * 16 * BPAD + (64 * wn + p * 16) * 2));
                bx[2 * p][0] = r[0]; bx[2 * p][1] = r[1];
                bx[2 * p + 1][0] = r[2]; bx[2 * p + 1][1] = r[3];
            }
            #pragma unroll
            for (int i = 0; i < 2; i++)
                ldsm4(af[i], aBc + aoff + (uint32_t)((32 * wm + 16 * i) * APAD + kk * 32));
            #pragma unroll
            for (int i = 0; i < 2; i++)
                #pragma unroll
                for (int j = 0; j < 8; j++)
                    mma16816(acc[i][j], af[i], bx[j][0], bx[j][1]);
        }
        // no trailing sync: next iter's writes target other ring slots, and the
        // slot written by issue at iter c+1 is protected by sync(c+1).
    }

    // ---- epilogue ----
    const int m4 = lane >> 2;
    const int n2 = (lane & 3) * 2;
    const bool do_hscat = HSCAT && (col0 == 0);

    float bcolv[16];
    #pragma unroll
    for (int j = 0; j < 8; j++) {
        if (bias) {
            float2 b2 = *(const float2*)(bias + col0 + 64 * wn + 8 * j + n2);
            bcolv[2 * j] = b2.x; bcolv[2 * j + 1] = b2.y;
        } else {
            bcolv[2 * j] = 0.f; bcolv[2 * j + 1] = 0.f;
        }
    }
    float csum[16], csq[16];
    if (STATS) {
        #pragma unroll
        for (int q = 0; q < 16; q++) { csum[q] = 0.f; csq[q] = 0.f; }
    }

    #pragma unroll
    for (int i = 0; i < 2; i++) {
        const int rb = row0 + 32 * wm + 16 * i + m4;
        #pragma unroll
        for (int hf = 0; hf < 2; hf++) {
            const int r = rb + 8 * hf;
            if (r >= M) continue;
            int si = 0, di = 0, gi2 = 0, sg = 0;
            if (GATH) { si = src[r]; di = dst[r]; gi2 = gid[si]; }
            if (SCAT) sg = seg[r];
            #pragma unroll
            for (int j = 0; j < 8; j++) {
                const int gc = col0 + 64 * wn + 8 * j + n2;
                float v0 = acc[i][j][2 * hf]     + bcolv[2 * j];
                float v1 = acc[i][j][2 * hf + 1] + bcolv[2 * j + 1];
                if (GATH) {
                    __half2 p1 = *(const __half2*)(Ph16 + (size_t)si * HID + gc);
                    __half2 p2 = *(const __half2*)(Ph16 + (size_t)di * HID + gc);
                    float2 f1 = __half22float2(p1);
                    float2 f2 = __half22float2(p2);
                    float2 g3 = *(const float2*)(U1 + (size_t)gi2 * HID + gc);
                    v0 += f1.x + f2.x + g3.x;
                    v1 += f1.y + f2.y + g3.y;
                }
                if (HALFC) {
                    *(uint32_t*)((__half*)Cvoid + (size_t)r * Nd + gc) = packh2(v0, v1);
                } else {
                    *(float2*)((float*)Cvoid + (size_t)r * Nd + gc) = make_float2(v0, v1);
                }
                if (SCAT) {
                    float* so = segout + (size_t)sg * Nd + gc;
                    atomicAdd(so, v0); atomicAdd(so + 1, v1);
                }
                if (do_hscat) {
                    float2 hv2 = *(const float2*)(Hg + (size_t)si * D + gc);
                    float* so2 = SHg + (size_t)di * D + gc;
                    atomicAdd(so2, hv2.x); atomicAdd(so2 + 1, hv2.y);
                }
                if (STATS) {
                    csum[2 * j] += v0;     csq[2 * j] += v0 * v0;
                    csum[2 * j + 1] += v1; csq[2 * j + 1] += v1 * v1;
                }
            }
        }
    }
    if (STATS) {
        #pragma unroll
        for (int j = 0; j < 8; j++) {
            const int cl0 = 64 * wn + 8 * j + n2;
            atomicAdd(&ssum[cl0], csum[2 * j]);
            atomicAdd(&ssum[cl0 + 1], csum[2 * j + 1]);
            atomicAdd(&ssq[cl0], csq[2 * j]);
            atomicAdd(&ssq[cl0 + 1], csq[2 * j + 1]);
        }
        __syncthreads();
        if (tid < 128) {
            atomicAdd(&st_sum[col0 + tid], ssum[tid]);
            atomicAdd(&st_sq[col0 + tid], ssq[tid]);
        }
    }
}

// ---------------------------------------------------------------------------
// Elementwise kernels
// ---------------------------------------------------------------------------
__global__ void zerok(float* __restrict__ p, size_t n) {
    size_t i = (size_t)blockIdx.x * blockDim.x + threadIdx.x;
    size_t st = (size_t)gridDim.x * blockDim.x;
    for (; i < n; i += st) p[i] = 0.f;
}

__global__ void bn_prep(float* __restrict__ sum, float* __restrict__ sq,
                        const float* __restrict__ g1, const float* __restrict__ beta1,
                        float* __restrict__ scale, float* __restrict__ shift, float invM)
{
    const int c = threadIdx.x;
    float mean = sum[c] * invM;
    float var  = sq[c] * invM - mean * mean;
    float rstd = rsqrtf(var + 1e-5f);
    float sc = rstd * g1[c];
    scale[c] = sc;
    shift[c] = beta1[c] - mean * sc;
    sum[c] = 0.f;
    sq[c] = 0.f;
}

__global__ void node_build(const float* __restrict__ h, const float* __restrict__ u,
                           const int* __restrict__ gid,
                           const float* __restrict__ SH, const float* __restrict__ SE,
                           __half* __restrict__ Xa16, float* __restrict__ UE, int N)
{
    int idx = blockIdx.x * blockDim.x + threadIdx.x;
    int tot = N * 32;
    if (idx >= tot) return;
    int n = idx >> 5;
    int c = (idx & 31) << 2;
    int g = gid[n];
    float4 sh = *(const float4*)&SH[(size_t)n * D + c];
    float4 hv = *(const float4*)&h[(size_t)n * D + c];
    float4 se = *(const float4*)&SE[(size_t)n * D + c];
    float4 uv = *(const float4*)&u[(size_t)g * D + c];
    size_t base = (size_t)n * HID;
    uint2 w;
    w.x = packh2(sh.x + hv.x, sh.y + hv.y);
    w.y = packh2(sh.z + hv.z, sh.w + hv.w);
    *(uint2*)&Xa16[base + c] = w;
    w.x = packh2(se.x, se.y);
    w.y = packh2(se.z, se.w);
    *(uint2*)&Xa16[base + D + c] = w;
    w.x = packh2(uv.x, uv.y);
    w.y = packh2(uv.z, uv.w);
    *(uint2*)&Xa16[base + 2 * D + c] = w;
    float* o = UE + (size_t)g * D + c;
    atomicAdd(o + 0, 0.5f * se.x); atomicAdd(o + 1, 0.5f * se.y);
    atomicAdd(o + 2, 0.5f * se.z); atomicAdd(o + 3, 0.5f * se.w);
}

__global__ void graph_build(const float* __restrict__ u, const float* __restrict__ UH,
                            const float* __restrict__ UE, __half* __restrict__ Xg16, int G)
{
    int idx = blockIdx.x * blockDim.x + threadIdx.x;
    int tot = G * 32;
    if (idx >= tot) return;
    int g = idx >> 5;
    int c = (idx & 31) << 2;
    size_t base = (size_t)g * HID;
    float4 a = *(const float4*)&UH[(size_t)g * D + c];
    float4 b = *(const float4*)&UE[(size_t)g * D + c];
    float4 d = *(const float4*)&u[(size_t)g * D + c];
    uint2 w;
    w.x = packh2(a.x, a.y); w.y = packh2(a.z, a.w);
    *(uint2*)&Xg16[base + c] = w;
    w.x = packh2(b.x, b.y); w.y = packh2(b.z, b.w);
    *(uint2*)&Xg16[base + D + c] = w;
    w.x = packh2(d.x, d.y); w.y = packh2(d.z, d.w);
    *(uint2*)&Xg16[base + 2 * D + c] = w;
}

// ---------------------------------------------------------------------------
// Dispatch.
// mode 0: HALFA plain            mode 5: HALFA + HALFC (Ph output fp16)
// mode 1: HALFA GATH+STATS+HSCAT mode 2: fp32 BNA+SCAT
// mode 3: HALFA STATS            mode 4: fp32 BNA
// ---------------------------------------------------------------------------
static void run_gemm_mma(int mode,
                         const void* A, const __half* Bp, const float* bias, void* C,
                         int M, int K, int Nd,
                         const float* sc, const float* sh,
                         const int* seg, float* segout,
                         const __half* Ph16, const float* U1,
                         const int* src, const int* dst, const int* gid,
                         float* st_sum, float* st_sq,
                         const float* Hg, float* SHg)
{
    dim3 grid(Nd / 128, (M + 127) / 128);
    switch (mode) {
    case 0:
        cudaFuncSetAttribute(gemm_mma<true ,false,false,false,false,false,false>, cudaFuncAttributeMaxDynamicSharedMemorySize, SMEM_BYTES);
        gemm_mma<true ,false,false,false,false,false,false><<<grid,256,SMEM_BYTES>>>(A,Bp,bias,C,M,K,Nd,sc,sh,seg,segout,Ph16,U1,src,dst,gid,st_sum,st_sq,Hg,SHg);
        break;
    case 5:
        cudaFuncSetAttribute(gemm_mma<true ,false,false,false,false,false,true >, cudaFuncAttributeMaxDynamicSharedMemorySize, SMEM_BYTES);
        gemm_mma<true ,false,false,false,false,false,true ><<<grid,256,SMEM_BYTES>>>(A,Bp,bias,C,M,K,Nd,sc,sh,seg,segout,Ph16,U1,src,dst,gid,st_sum,st_sq,Hg,SHg);
        break;
    case 1:
        cudaFuncSetAttribute(gemm_mma<true ,false,false,true ,true ,true ,false>, cudaFuncAttributeMaxDynamicSharedMemorySize, SMEM_BYTES);
        gemm_mma<true ,false,false,true ,true ,true ,false><<<grid,256,SMEM_BYTES>>>(A,Bp,bias,C,M,K,Nd,sc,sh,seg,segout,Ph16,U1,src,dst,gid,st_sum,st_sq,Hg,SHg);
        break;
    case 2:
        cudaFuncSetAttribute(gemm_mma<false,true ,true ,false,false,false,false>, cudaFuncAttributeMaxDynamicSharedMemorySize, SMEM_BYTES);
        gemm_mma<false,true ,true ,false,false,false,false><<<grid,256,SMEM_BYTES>>>(A,Bp,bias,C,M,K,Nd,sc,sh,seg,segout,Ph16,U1,src,dst,gid,st_sum,st_sq,Hg,SHg);
        break;
    case 3:
        cudaFuncSetAttribute(gemm_mma<true ,false,false,false,true ,false,false>, cudaFuncAttributeMaxDynamicSharedMemorySize, SMEM_BYTES);
        gemm_mma<true ,false,false,false,true ,false,false><<<grid,256,SMEM_BYTES>>>(A,Bp,bias,C,M,K,Nd,sc,sh,seg,segout,Ph16,U1,src,dst,gid,st_sum,st_sq,Hg,SHg);
        break;
    case 4:
        cudaFuncSetAttribute(gemm_mma<false,true ,false,false,false,false,false>, cudaFuncAttributeMaxDynamicSharedMemorySize, SMEM_BYTES);
        gemm_mma<false,true ,false,false,false,false,false><<<grid,256,SMEM_BYTES>>>(A,Bp,bias,C,M,K,Nd,sc,sh,seg,segout,Ph16,U1,src,dst,gid,st_sum,st_sq,Hg,SHg);
        break;
    }
}

extern "C" void kernel_launch(void* const* d_in, const int* in_sizes, int n_in,
                              void* d_out, int out_size)
{
    const float* h   = (const float*)d_in[0];
    const float* e   = (const float*)d_in[1];
    const float* u   = (const float*)d_in[2];
    const int*   src = (const int*)d_in[3];
    const int*   dst = (const int*)d_in[4];
    const int*   gid = (const int*)d_in[5];

    const float* bW1 = (const float*)d_in[6];
    const float* bb1 = (const float*)d_in[7];
    const float* bg1 = (const float*)d_in[8];
    const float* bbt = (const float*)d_in[9];
    const float* bW2 = (const float*)d_in[10];
    const float* bb2 = (const float*)d_in[11];

    const float* aW1 = (const float*)d_in[12];
    const float* ab1 = (const float*)d_in[13];
    const float* ag1 = (const float*)d_in[14];
    const float* abt = (const float*)d_in[15];
    const float* aW2 = (const float*)d_in[16];
    const float* ab2 = (const float*)d_in[17];

    const float* gW1 = (const float*)d_in[18];
    const float* gb1 = (const float*)d_in[19];
    const float* gg1 = (const float*)d_in[20];
    const float* gbt = (const float*)d_in[21];
    const float* gW2 = (const float*)d_in[22];
    const float* gb2 = (const float*)d_in[23];

    const int N = in_sizes[5];
    const int E = in_sizes[3];
    const int G = in_sizes[2] / D;

    float* scratch = nullptr;
    cudaGetSymbolAddress((void**)&scratch, g_scratch);

    float* Zb = scratch + OFF_ZB;
    __half* Ph16 = (__half*)(scratch + OFF_PH);
    float* U1 = scratch + OFF_U1;
    float* Za = scratch + OFF_ZA;
    float* Zg = scratch + OFF_ZG;
    float* SH = scratch + OFF_SH;
    float* SE = scratch + OFF_SE;
    float* UH = scratch + OFF_UH;
    float* UE = scratch + OFF_UE;
    float* st_sum   = scratch + OFF_ST;
    float* st_sq    = st_sum + HID;
    float* bn_scale = st_sq + HID;
    float* bn_shift = bn_scale + HID;
    __half* WP   = (__half*)(scratch + OFF_WP);
    __half* Xa16 = (__half*)(scratch + OFF_XA16);
    __half* Xg16 = (__half*)(scratch + OFF_XG16);
    __half* e16  = (__half*)(scratch + OFF_E16);
    __half* h16  = (__half*)(scratch + OFF_H16);
    __half* u16  = (__half*)(scratch + OFF_U16);

    float* out_h = (float*)d_out;
    float* out_e = out_h + (size_t)N * D;
    float* out_u = out_e + (size_t)E * D;

    // Launch 1: zero accumulators (SH, SE, UH, UE, stats).
    {
        size_t nz = (size_t)MAXN * D * 2 + (size_t)MAXG * D * 2 + 2 * HID;
        zerok<<<2048, 256>>>(SH, nz);
    }
    // Launch 2: fused input converts.
    {
        int ne4 = E * D / 4, nh4 = N * D / 4, nu4 = G * D / 4;
        cvt_all<<<(ne4 + nh4 + nu4 + 255) / 256, 256>>>(e, h, u, e16, h16, u16, ne4, nh4, nu4);
    }
    // Launch 3: fused weight prep.
    prep_all<<<(3 * T1 + 3 * T3 + 2 * T2 + 255) / 256, 256>>>(bW1, bW2, aW1, aW2, gW1, gW2, WP);

    // ---- Bond path ----
    // Launch 4: Ph16 = fp16(h16 @ bW1a)
    run_gemm_mma(5, h16, WP + WPO_BW1A, nullptr, Ph16, N, 128, HID,
                 nullptr, nullptr, nullptr, nullptr, nullptr, nullptr, nullptr, nullptr, nullptr,
                 nullptr, nullptr, nullptr, nullptr);
    // Launch 5: U1
    run_gemm_mma(0, u16, WP + WPO_BW1C, bb1, U1, G, 128, HID,
                 nullptr, nullptr, nullptr, nullptr, nullptr, nullptr, nullptr, nullptr, nullptr,
                 nullptr, nullptr, nullptr, nullptr);
    // Launch 6 (ncu -s 5 captures this): the big fused e-GEMM.
    run_gemm_mma(1, e16, WP + WPO_BW1B, nullptr, Zb, E, 128, HID,
                 nullptr, nullptr, nullptr, nullptr, Ph16, U1, src, dst, gid, st_sum, st_sq,
                 h, SH);
    bn_prep<<<1, HID>>>(st_sum, st_sq, bg1, bbt, bn_scale, bn_shift, 1.f / (float)E);
    run_gemm_mma(2, Zb, WP + WPO_BW2, bb2, out_e, E, HID, D,
                 bn_scale, bn_shift, dst, SE, nullptr, nullptr, nullptr, nullptr, nullptr,
                 nullptr, nullptr, nullptr, nullptr);

    // ---- Atom path ----
    node_build<<<(N * 32 + 255) / 256, 256>>>(h, u, gid, SH, SE, Xa16, UE, N);
    run_gemm_mma(3, Xa16, WP + WPO_AW1, ab1, Za, N, HID, HID,
                 nullptr, nullptr, nullptr, nullptr, nullptr, nullptr, nullptr, nullptr, nullptr,
                 st_sum, st_sq, nullptr, nullptr);
    bn_prep<<<1, HID>>>(st_sum, st_sq, ag1, abt, bn_scale, bn_shift, 1.f / (float)N);
    run_gemm_mma(2, Za, WP + WPO_AW2, ab2, out_h, N, HID, D,
                 bn_scale, bn_shift, gid, UH, nullptr, nullptr, nullptr, nullptr, nullptr,
                 nullptr, nullptr, nullptr, nullptr);

    // ---- Global path ----
    graph_build<<<(G * 32 + 255) / 256, 256>>>(u, UH, UE, Xg16, G);
    run_gemm_mma(3, Xg16, WP + WPO_GW1, gb1, Zg, G, HID, HID,
                 nullptr, nullptr, nullptr, nullptr, nullptr, nullptr, nullptr, nullptr, nullptr,
                 st_sum, st_sq, nullptr, nullptr);
    bn_prep<<<1, HID>>>(st_sum, st_sq, gg1, gbt, bn_scale, bn_shift, 1.f / (float)G);
    run_gemm_mma(4, Zg, WP + WPO_GW2, gb2, out_u, G, HID, D,
                 bn_scale, bn_shift, nullptr, nullptr, nullptr, nullptr, nullptr, nullptr, nullptr,
                 nullptr, nullptr, nullptr, nullptr);
}